// round 1
// baseline (speedup 1.0000x reference)
#include <cuda_runtime.h>
#include <cstdint>

#define NN 100000
#define EE 1600000

// Scratch (allocation-free rule: __device__ globals)
__device__ float g_deg[NN];
__device__ float g_agg[(size_t)NN * 128];   // layer-1 neighbor sums
__device__ float g_h[(size_t)NN * 128];     // hidden activations
__device__ float g_agg2[(size_t)NN * 128];  // layer-2 neighbor sums

// ---------------------------------------------------------------------------
// Init: zero deg + both accumulators
// ---------------------------------------------------------------------------
__global__ void k_init() {
    int i = blockIdx.x * 256 + threadIdx.x;
    const int n4 = NN * 128 / 4;  // 3,200,000 float4s
    if (i < n4) {
        float4 z = make_float4(0.f, 0.f, 0.f, 0.f);
        ((float4*)g_agg)[i] = z;
        ((float4*)g_agg2)[i] = z;
    }
    if (i < NN) g_deg[i] = 0.f;
}

// ---------------------------------------------------------------------------
// Scatter 1: one warp per edge; gather x[src] row (float4/lane), vector-red
// into g_agg[dst]; lane 0 bumps degree.
// ---------------------------------------------------------------------------
__global__ void k_scatter1(const float* __restrict__ x,
                           const int* __restrict__ src,
                           const int* __restrict__ dst) {
    int t = blockIdx.x * 256 + threadIdx.x;
    int e = t >> 5;
    if (e >= EE) return;
    int lane = t & 31;
    int s = __ldg(src + e);
    int d = __ldg(dst + e);
    if (lane == 0) atomicAdd(g_deg + d, 1.f);
    float4 v = *(const float4*)(x + (size_t)s * 128 + lane * 4);
    float* p = g_agg + (size_t)d * 128 + lane * 4;
    asm volatile("red.global.add.v4.f32 [%0], {%1,%2,%3,%4};"
                 :: "l"(p), "f"(v.x), "f"(v.y), "f"(v.z), "f"(v.w) : "memory");
}

// Scatter 2: same, h -> agg2, no degree.
__global__ void k_scatter2(const int* __restrict__ src,
                           const int* __restrict__ dst) {
    int t = blockIdx.x * 256 + threadIdx.x;
    int e = t >> 5;
    if (e >= EE) return;
    int lane = t & 31;
    int s = __ldg(src + e);
    int d = __ldg(dst + e);
    float4 v = *(const float4*)(g_h + (size_t)s * 128 + lane * 4);
    float* p = g_agg2 + (size_t)d * 128 + lane * 4;
    asm volatile("red.global.add.v4.f32 [%0], {%1,%2,%3,%4};"
                 :: "l"(p), "f"(v.x), "f"(v.y), "f"(v.z), "f"(v.w) : "memory");
}

// ---------------------------------------------------------------------------
// Layer 1: h = relu(((agg + x) / (deg+1)) @ W1 + b1)
// Block: 64 nodes x 128 cols. 256 threads; thread = 4 nodes x 8 cols.
// smem: W1 full (64KB) + fused A tile 64x132 (padded) + rinv[64]  -> ~97KB dyn.
// ---------------------------------------------------------------------------
__global__ __launch_bounds__(256, 2) void k_layer1(const float* __restrict__ x,
                                                   const float* __restrict__ W1,
                                                   const float* __restrict__ b1) {
    extern __shared__ float sm[];
    float* Ws = sm;            // 128*128 = 16384 floats
    float* As = sm + 16384;    // 64*132  = 8448 floats
    float* rv = As + 8448;     // 64 floats

    int tid = threadIdx.x;
    int n0 = blockIdx.x * 64;

    #pragma unroll
    for (int i = tid; i < 4096; i += 256)
        ((float4*)Ws)[i] = ((const float4*)W1)[i];

    if (tid < 64) {
        int gn = n0 + tid;
        rv[tid] = (gn < NN) ? (1.f / (g_deg[gn] + 1.f)) : 0.f;
    }
    __syncthreads();

    // Fused A tile: (x + agg) * rinv, padded stride 132 (float4-aligned)
    for (int i = tid; i < 2048; i += 256) {
        int n = i >> 5, k4 = i & 31;
        int gn = n0 + n;
        float4 v = make_float4(0.f, 0.f, 0.f, 0.f);
        if (gn < NN) {
            float4 xv = ((const float4*)(x + (size_t)gn * 128))[k4];
            float4 av = ((const float4*)(g_agg + (size_t)gn * 128))[k4];
            float r = rv[n];
            v.x = (xv.x + av.x) * r;
            v.y = (xv.y + av.y) * r;
            v.z = (xv.z + av.z) * r;
            v.w = (xv.w + av.w) * r;
        }
        *((float4*)(As + n * 132 + k4 * 4)) = v;
    }
    __syncthreads();

    int tx = tid & 15, ty = tid >> 4;
    float acc[4][8];
    #pragma unroll
    for (int i = 0; i < 4; i++)
        #pragma unroll
        for (int j = 0; j < 8; j++) acc[i][j] = 0.f;

    const float* A0 = As + (ty * 4) * 132;
    #pragma unroll 8
    for (int k = 0; k < 128; k++) {
        float aa[4];
        aa[0] = A0[k]; aa[1] = A0[k + 132]; aa[2] = A0[k + 264]; aa[3] = A0[k + 396];
        float4 bv0 = *(const float4*)(Ws + k * 128 + tx * 8);
        float4 bv1 = *(const float4*)(Ws + k * 128 + tx * 8 + 4);
        float bb[8] = {bv0.x, bv0.y, bv0.z, bv0.w, bv1.x, bv1.y, bv1.z, bv1.w};
        #pragma unroll
        for (int i = 0; i < 4; i++)
            #pragma unroll
            for (int j = 0; j < 8; j++) acc[i][j] = fmaf(aa[i], bb[j], acc[i][j]);
    }

    float bb[8];
    #pragma unroll
    for (int j = 0; j < 8; j++) bb[j] = __ldg(b1 + tx * 8 + j);

    #pragma unroll
    for (int i = 0; i < 4; i++) {
        int gn = n0 + ty * 4 + i;
        if (gn < NN) {
            float4 o0, o1;
            o0.x = fmaxf(acc[i][0] + bb[0], 0.f);
            o0.y = fmaxf(acc[i][1] + bb[1], 0.f);
            o0.z = fmaxf(acc[i][2] + bb[2], 0.f);
            o0.w = fmaxf(acc[i][3] + bb[3], 0.f);
            o1.x = fmaxf(acc[i][4] + bb[4], 0.f);
            o1.y = fmaxf(acc[i][5] + bb[5], 0.f);
            o1.z = fmaxf(acc[i][6] + bb[6], 0.f);
            o1.w = fmaxf(acc[i][7] + bb[7], 0.f);
            *((float4*)(g_h + (size_t)gn * 128 + tx * 8)) = o0;
            *((float4*)(g_h + (size_t)gn * 128 + tx * 8 + 4)) = o1;
        }
    }
}

// ---------------------------------------------------------------------------
// Layer 2: out = h @ W2s + b2 + (agg2/max(deg,1)) @ W2n
// Block: 64 nodes x 64 cols, 2 K-phases (h@W2s then m@W2n) reusing smem.
// Thread = 4 nodes x 4 cols.
// ---------------------------------------------------------------------------
__global__ __launch_bounds__(256, 2) void k_layer2(const float* __restrict__ W2n,
                                                   const float* __restrict__ W2s,
                                                   const float* __restrict__ b2,
                                                   float* __restrict__ out) {
    extern __shared__ float sm[];
    float* Ws = sm;            // 128*64 = 8192 floats
    float* As = sm + 8192;     // 64*132 = 8448 floats
    float* rv = As + 8448;     // 64 floats

    int tid = threadIdx.x;
    int n0 = blockIdx.x * 64;

    if (tid < 64) {
        int gn = n0 + tid;
        rv[tid] = (gn < NN) ? (1.f / fmaxf(g_deg[gn], 1.f)) : 0.f;
    }

    int tx = tid & 15, ty = tid >> 4;
    float acc[4][4];
    #pragma unroll
    for (int i = 0; i < 4; i++)
        #pragma unroll
        for (int j = 0; j < 4; j++) acc[i][j] = 0.f;

    for (int p = 0; p < 2; p++) {
        __syncthreads();  // protects smem reuse; publishes rv before p=1 use
        const float* W = p ? W2n : W2s;
        for (int i = tid; i < 2048; i += 256)
            ((float4*)Ws)[i] = ((const float4*)W)[i];
        for (int i = tid; i < 2048; i += 256) {
            int n = i >> 5, k4 = i & 31;
            int gn = n0 + n;
            float4 v = make_float4(0.f, 0.f, 0.f, 0.f);
            if (gn < NN) {
                if (p == 0) {
                    v = ((const float4*)(g_h + (size_t)gn * 128))[k4];
                } else {
                    float4 av = ((const float4*)(g_agg2 + (size_t)gn * 128))[k4];
                    float r = rv[n];
                    v.x = av.x * r; v.y = av.y * r; v.z = av.z * r; v.w = av.w * r;
                }
            }
            *((float4*)(As + n * 132 + k4 * 4)) = v;
        }
        __syncthreads();

        const float* A0 = As + (ty * 4) * 132;
        #pragma unroll 8
        for (int k = 0; k < 128; k++) {
            float aa[4];
            aa[0] = A0[k]; aa[1] = A0[k + 132]; aa[2] = A0[k + 264]; aa[3] = A0[k + 396];
            float4 bv = *(const float4*)(Ws + k * 64 + tx * 4);
            float bb[4] = {bv.x, bv.y, bv.z, bv.w};
            #pragma unroll
            for (int i = 0; i < 4; i++)
                #pragma unroll
                for (int j = 0; j < 4; j++) acc[i][j] = fmaf(aa[i], bb[j], acc[i][j]);
        }
    }

    float bb[4];
    #pragma unroll
    for (int j = 0; j < 4; j++) bb[j] = __ldg(b2 + tx * 4 + j);

    #pragma unroll
    for (int i = 0; i < 4; i++) {
        int gn = n0 + ty * 4 + i;
        if (gn < NN) {
            float4 o;
            o.x = acc[i][0] + bb[0];
            o.y = acc[i][1] + bb[1];
            o.z = acc[i][2] + bb[2];
            o.w = acc[i][3] + bb[3];
            *((float4*)(out + (size_t)gn * 64 + tx * 4)) = o;
        }
    }
}

// ---------------------------------------------------------------------------
extern "C" void kernel_launch(void* const* d_in, const int* in_sizes, int n_in,
                              void* d_out, int out_size) {
    const float* x   = (const float*)d_in[0];
    const float* W1  = (const float*)d_in[1];
    const float* b1  = (const float*)d_in[2];
    const float* W2n = (const float*)d_in[3];
    const float* W2s = (const float*)d_in[4];
    const float* b2  = (const float*)d_in[5];
    const int*   ei  = (const int*)d_in[6];
    const int* src = ei;
    const int* dst = ei + EE;

    const int smem1 = (16384 + 8448 + 64) * 4;  // 99584 B
    const int smem2 = (8192 + 8448 + 64) * 4;   // 66816 B
    cudaFuncSetAttribute(k_layer1, cudaFuncAttributeMaxDynamicSharedMemorySize, smem1);
    cudaFuncSetAttribute(k_layer2, cudaFuncAttributeMaxDynamicSharedMemorySize, smem2);

    k_init<<<12500, 256>>>();
    k_scatter1<<<(EE * 32) / 256, 256>>>(x, src, dst);
    k_layer1<<<(NN + 63) / 64, 256, smem1>>>(x, W1, b1);
    k_scatter2<<<(EE * 32) / 256, 256>>>(src, dst);
    k_layer2<<<(NN + 63) / 64, 256, smem2>>>(W2n, W2s, b2, (float*)d_out);
}

// round 2
// speedup vs baseline: 1.4452x; 1.4452x over previous
#include <cuda_runtime.h>
#include <cstdint>

#define NN 100000
#define EE 1600000
#define NB_SCAN 98   // ceil(NN/1024)

// ---------------- scratch (__device__ globals; no allocation allowed) ------
__device__ int   g_cnt[NN];
__device__ int   g_rs[NN];        // CSR row start (exclusive prefix of cnt)
__device__ int   g_cur[NN];       // fill cursors
__device__ int   g_bsum[NB_SCAN];
__device__ float g_rinv1[NN];     // 1/(deg+1)
__device__ float g_rinv2[NN];     // 1/max(deg,1)
__device__ int   g_csr[EE];       // src ids grouped by dst
__device__ float g_hin[(size_t)NN * 128];  // normalized layer-1 input
__device__ float g_h[(size_t)NN * 128];    // hidden activations
__device__ float g_y2[(size_t)NN * 64];    // h @ W2n
__device__ float g_z[(size_t)NN * 64];     // h @ W2s + b2

// ---------------------------------------------------------------------------
// CSR build
// ---------------------------------------------------------------------------
__global__ void k_zero() {
    int i = blockIdx.x * 256 + threadIdx.x;
    if (i < NN) g_cnt[i] = 0;
}

__global__ void k_hist(const int* __restrict__ dst) {
    int e = blockIdx.x * 256 + threadIdx.x;
    if (e < EE) atomicAdd(&g_cnt[__ldg(dst + e)], 1);
}

__global__ void k_scan1() {
    __shared__ int s[1024];
    int t = threadIdx.x;
    int i = blockIdx.x * 1024 + t;
    int v = (i < NN) ? g_cnt[i] : 0;
    s[t] = v;
    __syncthreads();
    #pragma unroll
    for (int off = 1; off < 1024; off <<= 1) {
        int u = (t >= off) ? s[t - off] : 0;
        __syncthreads();
        s[t] += u;
        __syncthreads();
    }
    if (i < NN) g_rs[i] = s[t] - v;           // exclusive, partial
    if (t == 1023) g_bsum[blockIdx.x] = s[1023];
}

__global__ void k_scan2() {
    if (threadIdx.x == 0) {
        int acc = 0;
        for (int b = 0; b < NB_SCAN; b++) {
            int v = g_bsum[b];
            g_bsum[b] = acc;
            acc += v;
        }
    }
}

__global__ void k_scan3() {
    int i = blockIdx.x * 256 + threadIdx.x;
    if (i >= NN) return;
    int rs = g_rs[i] + g_bsum[i >> 10];
    g_rs[i] = rs;
    g_cur[i] = rs;
    float c = (float)g_cnt[i];
    g_rinv1[i] = 1.f / (c + 1.f);
    g_rinv2[i] = 1.f / fmaxf(c, 1.f);
}

__global__ void k_fill(const int* __restrict__ src, const int* __restrict__ dst) {
    int e = blockIdx.x * 256 + threadIdx.x;
    if (e >= EE) return;
    int d = __ldg(dst + e);
    int pos = atomicAdd(&g_cur[d], 1);
    g_csr[pos] = __ldg(src + e);
}

// ---------------------------------------------------------------------------
// Aggregation 1: warp per node. g_hin[i] = (x_i + sum_{j in N(i)} x_j)/(deg+1)
// ---------------------------------------------------------------------------
__global__ __launch_bounds__(256) void k_agg1(const float* __restrict__ x) {
    int w = blockIdx.x * 8 + (threadIdx.x >> 5);
    if (w >= NN) return;
    int lane = threadIdx.x & 31;
    int beg = __ldg(g_rs + w);
    int cnt = __ldg(g_cnt + w);
    float rinv = __ldg(g_rinv1 + w);

    float4 acc = *(const float4*)(x + (size_t)w * 128 + lane * 4);  // self
    int j = 0;
    for (; j + 4 <= cnt; j += 4) {
        int s0 = __ldg(g_csr + beg + j);
        int s1 = __ldg(g_csr + beg + j + 1);
        int s2 = __ldg(g_csr + beg + j + 2);
        int s3 = __ldg(g_csr + beg + j + 3);
        float4 v0 = *(const float4*)(x + (size_t)s0 * 128 + lane * 4);
        float4 v1 = *(const float4*)(x + (size_t)s1 * 128 + lane * 4);
        float4 v2 = *(const float4*)(x + (size_t)s2 * 128 + lane * 4);
        float4 v3 = *(const float4*)(x + (size_t)s3 * 128 + lane * 4);
        acc.x += (v0.x + v1.x) + (v2.x + v3.x);
        acc.y += (v0.y + v1.y) + (v2.y + v3.y);
        acc.z += (v0.z + v1.z) + (v2.z + v3.z);
        acc.w += (v0.w + v1.w) + (v2.w + v3.w);
    }
    for (; j < cnt; j++) {
        int s0 = __ldg(g_csr + beg + j);
        float4 v0 = *(const float4*)(x + (size_t)s0 * 128 + lane * 4);
        acc.x += v0.x; acc.y += v0.y; acc.z += v0.z; acc.w += v0.w;
    }
    acc.x *= rinv; acc.y *= rinv; acc.z *= rinv; acc.w *= rinv;
    *((float4*)(g_hin + (size_t)w * 128 + lane * 4)) = acc;
}

// ---------------------------------------------------------------------------
// Layer 1 GEMM: h = relu(g_hin @ W1 + b1).  64 nodes x 128 cols per block.
// ---------------------------------------------------------------------------
__global__ __launch_bounds__(256, 2) void k_layer1(const float* __restrict__ W1,
                                                   const float* __restrict__ b1) {
    extern __shared__ float sm[];
    float* Ws = sm;          // 128*128
    float* As = sm + 16384;  // 64*132

    int tid = threadIdx.x;
    int n0 = blockIdx.x * 64;

    for (int i = tid; i < 4096; i += 256)
        ((float4*)Ws)[i] = ((const float4*)W1)[i];

    for (int i = tid; i < 2048; i += 256) {
        int n = i >> 5, k4 = i & 31;
        int gn = n0 + n;
        float4 v = make_float4(0.f, 0.f, 0.f, 0.f);
        if (gn < NN) v = ((const float4*)(g_hin + (size_t)gn * 128))[k4];
        *((float4*)(As + n * 132 + k4 * 4)) = v;
    }
    __syncthreads();

    int tx = tid & 15, ty = tid >> 4;
    float acc[4][8];
    #pragma unroll
    for (int i = 0; i < 4; i++)
        #pragma unroll
        for (int j = 0; j < 8; j++) acc[i][j] = 0.f;

    const float* A0 = As + (ty * 4) * 132;
    #pragma unroll 8
    for (int k = 0; k < 128; k++) {
        float aa[4];
        aa[0] = A0[k]; aa[1] = A0[k + 132]; aa[2] = A0[k + 264]; aa[3] = A0[k + 396];
        float4 bv0 = *(const float4*)(Ws + k * 128 + tx * 8);
        float4 bv1 = *(const float4*)(Ws + k * 128 + tx * 8 + 4);
        float bb[8] = {bv0.x, bv0.y, bv0.z, bv0.w, bv1.x, bv1.y, bv1.z, bv1.w};
        #pragma unroll
        for (int i = 0; i < 4; i++)
            #pragma unroll
            for (int j = 0; j < 8; j++) acc[i][j] = fmaf(aa[i], bb[j], acc[i][j]);
    }

    float bb[8];
    #pragma unroll
    for (int j = 0; j < 8; j++) bb[j] = __ldg(b1 + tx * 8 + j);

    #pragma unroll
    for (int i = 0; i < 4; i++) {
        int gn = n0 + ty * 4 + i;
        if (gn < NN) {
            float4 o0, o1;
            o0.x = fmaxf(acc[i][0] + bb[0], 0.f);
            o0.y = fmaxf(acc[i][1] + bb[1], 0.f);
            o0.z = fmaxf(acc[i][2] + bb[2], 0.f);
            o0.w = fmaxf(acc[i][3] + bb[3], 0.f);
            o1.x = fmaxf(acc[i][4] + bb[4], 0.f);
            o1.y = fmaxf(acc[i][5] + bb[5], 0.f);
            o1.z = fmaxf(acc[i][6] + bb[6], 0.f);
            o1.w = fmaxf(acc[i][7] + bb[7], 0.f);
            *((float4*)(g_h + (size_t)gn * 128 + tx * 8)) = o0;
            *((float4*)(g_h + (size_t)gn * 128 + tx * 8 + 4)) = o1;
        }
    }
}

// ---------------------------------------------------------------------------
// Layer 2 GEMMs fused: z = h@W2s + b2 (cols 0..63), y2 = h@W2n (cols 64..127)
// B = [W2s | W2n] packed into smem as 128x128. Same tiling as layer1.
// ---------------------------------------------------------------------------
__global__ __launch_bounds__(256, 2) void k_layer2ab(const float* __restrict__ W2n,
                                                     const float* __restrict__ W2s,
                                                     const float* __restrict__ b2) {
    extern __shared__ float sm[];
    float* Ws = sm;          // 128*128
    float* As = sm + 16384;  // 64*132

    int tid = threadIdx.x;
    int n0 = blockIdx.x * 64;

    for (int i = tid; i < 4096; i += 256) {
        int k = i >> 5, c4 = i & 31;
        float4 v = (c4 < 16) ? ((const float4*)(W2s + k * 64))[c4]
                             : ((const float4*)(W2n + k * 64))[c4 - 16];
        ((float4*)Ws)[i] = v;
    }

    for (int i = tid; i < 2048; i += 256) {
        int n = i >> 5, k4 = i & 31;
        int gn = n0 + n;
        float4 v = make_float4(0.f, 0.f, 0.f, 0.f);
        if (gn < NN) v = ((const float4*)(g_h + (size_t)gn * 128))[k4];
        *((float4*)(As + n * 132 + k4 * 4)) = v;
    }
    __syncthreads();

    int tx = tid & 15, ty = tid >> 4;
    float acc[4][8];
    #pragma unroll
    for (int i = 0; i < 4; i++)
        #pragma unroll
        for (int j = 0; j < 8; j++) acc[i][j] = 0.f;

    const float* A0 = As + (ty * 4) * 132;
    #pragma unroll 8
    for (int k = 0; k < 128; k++) {
        float aa[4];
        aa[0] = A0[k]; aa[1] = A0[k + 132]; aa[2] = A0[k + 264]; aa[3] = A0[k + 396];
        float4 bv0 = *(const float4*)(Ws + k * 128 + tx * 8);
        float4 bv1 = *(const float4*)(Ws + k * 128 + tx * 8 + 4);
        float bb[8] = {bv0.x, bv0.y, bv0.z, bv0.w, bv1.x, bv1.y, bv1.z, bv1.w};
        #pragma unroll
        for (int i = 0; i < 4; i++)
            #pragma unroll
            for (int j = 0; j < 8; j++) acc[i][j] = fmaf(aa[i], bb[j], acc[i][j]);
    }

    bool isZ = (tx < 8);  // cols 0..63 -> z (+bias), cols 64..127 -> y2
    float bb[8];
    #pragma unroll
    for (int j = 0; j < 8; j++) bb[j] = isZ ? __ldg(b2 + tx * 8 + j) : 0.f;
    float* outp = isZ ? g_z : g_y2;
    int cbase = isZ ? tx * 8 : (tx - 8) * 8;

    #pragma unroll
    for (int i = 0; i < 4; i++) {
        int gn = n0 + ty * 4 + i;
        if (gn < NN) {
            float4 o0, o1;
            o0.x = acc[i][0] + bb[0]; o0.y = acc[i][1] + bb[1];
            o0.z = acc[i][2] + bb[2]; o0.w = acc[i][3] + bb[3];
            o1.x = acc[i][4] + bb[4]; o1.y = acc[i][5] + bb[5];
            o1.z = acc[i][6] + bb[6]; o1.w = acc[i][7] + bb[7];
            *((float4*)(outp + (size_t)gn * 64 + cbase)) = o0;
            *((float4*)(outp + (size_t)gn * 64 + cbase + 4)) = o1;
        }
    }
}

// ---------------------------------------------------------------------------
// Aggregation 2 + epilogue: out = z + (sum_{j in N(i)} y2_j) * rinv2
// Warp per node, float2 per lane (row = 64 floats).
// ---------------------------------------------------------------------------
__global__ __launch_bounds__(256) void k_agg2out(float* __restrict__ out) {
    int w = blockIdx.x * 8 + (threadIdx.x >> 5);
    if (w >= NN) return;
    int lane = threadIdx.x & 31;
    int beg = __ldg(g_rs + w);
    int cnt = __ldg(g_cnt + w);
    float rinv = __ldg(g_rinv2 + w);

    float2 acc = make_float2(0.f, 0.f);
    int j = 0;
    for (; j + 4 <= cnt; j += 4) {
        int s0 = __ldg(g_csr + beg + j);
        int s1 = __ldg(g_csr + beg + j + 1);
        int s2 = __ldg(g_csr + beg + j + 2);
        int s3 = __ldg(g_csr + beg + j + 3);
        float2 v0 = *(const float2*)(g_y2 + (size_t)s0 * 64 + lane * 2);
        float2 v1 = *(const float2*)(g_y2 + (size_t)s1 * 64 + lane * 2);
        float2 v2 = *(const float2*)(g_y2 + (size_t)s2 * 64 + lane * 2);
        float2 v3 = *(const float2*)(g_y2 + (size_t)s3 * 64 + lane * 2);
        acc.x += (v0.x + v1.x) + (v2.x + v3.x);
        acc.y += (v0.y + v1.y) + (v2.y + v3.y);
    }
    for (; j < cnt; j++) {
        int s0 = __ldg(g_csr + beg + j);
        float2 v0 = *(const float2*)(g_y2 + (size_t)s0 * 64 + lane * 2);
        acc.x += v0.x; acc.y += v0.y;
    }
    float2 z = *(const float2*)(g_z + (size_t)w * 64 + lane * 2);
    float2 o;
    o.x = z.x + acc.x * rinv;
    o.y = z.y + acc.y * rinv;
    *((float2*)(out + (size_t)w * 64 + lane * 2)) = o;
}

// ---------------------------------------------------------------------------
extern "C" void kernel_launch(void* const* d_in, const int* in_sizes, int n_in,
                              void* d_out, int out_size) {
    const float* x   = (const float*)d_in[0];
    const float* W1  = (const float*)d_in[1];
    const float* b1  = (const float*)d_in[2];
    const float* W2n = (const float*)d_in[3];
    const float* W2s = (const float*)d_in[4];
    const float* b2  = (const float*)d_in[5];
    const int*   ei  = (const int*)d_in[6];
    const int* src = ei;
    const int* dst = ei + EE;

    const int smemG = (16384 + 8448) * 4;  // 99328 B
    cudaFuncSetAttribute(k_layer1, cudaFuncAttributeMaxDynamicSharedMemorySize, smemG);
    cudaFuncSetAttribute(k_layer2ab, cudaFuncAttributeMaxDynamicSharedMemorySize, smemG);

    // CSR build
    k_zero<<<(NN + 255) / 256, 256>>>();
    k_hist<<<(EE + 255) / 256, 256>>>(dst);
    k_scan1<<<NB_SCAN, 1024>>>();
    k_scan2<<<1, 32>>>();
    k_scan3<<<(NN + 255) / 256, 256>>>();
    k_fill<<<(EE + 255) / 256, 256>>>(src, dst);

    // Layer 1
    k_agg1<<<(NN + 7) / 8, 256>>>(x);
    k_layer1<<<(NN + 63) / 64, 256, smemG>>>(W1, b1);

    // Layer 2 (W2n pushed before aggregation)
    k_layer2ab<<<(NN + 63) / 64, 256, smemG>>>(W2n, W2s, b2);
    k_agg2out<<<(NN + 7) / 8, 256>>>((float*)d_out);
}

// round 7
// speedup vs baseline: 1.8170x; 1.2573x over previous
#include <cuda_runtime.h>
#include <cstdint>

#define NN 100000
#define EE 1600000
#define NB_SCAN 98   // ceil(NN/1024)

// ---------------- scratch (__device__ globals; no allocation allowed) ------
__device__ int   g_cnt[NN];
__device__ int   g_rs[NN];
__device__ int   g_cur[NN];
__device__ int   g_bsum[NB_SCAN];
__device__ float g_rinv1[NN];
__device__ float g_rinv2[NN];
__device__ int   g_csr[EE];
__device__ float g_hin[(size_t)NN * 128];
__device__ float g_h[(size_t)NN * 128];
__device__ float g_y2[(size_t)NN * 64];
__device__ float g_z[(size_t)NN * 64];

// ---------------------------------------------------------------------------
// CSR build
// ---------------------------------------------------------------------------
__global__ void k_zero() {
    int i = blockIdx.x * 256 + threadIdx.x;
    if (i < NN) g_cnt[i] = 0;
}

__global__ void k_hist(const int* __restrict__ dst) {
    int e = blockIdx.x * 256 + threadIdx.x;
    if (e < EE) atomicAdd(&g_cnt[__ldg(dst + e)], 1);
}

__global__ void k_scan1() {
    __shared__ int s[1024];
    int t = threadIdx.x;
    int i = blockIdx.x * 1024 + t;
    int v = (i < NN) ? g_cnt[i] : 0;
    s[t] = v;
    __syncthreads();
    #pragma unroll
    for (int off = 1; off < 1024; off <<= 1) {
        int u = (t >= off) ? s[t - off] : 0;
        __syncthreads();
        s[t] += u;
        __syncthreads();
    }
    if (i < NN) g_rs[i] = s[t] - v;
    if (t == 1023) g_bsum[blockIdx.x] = s[1023];
}

// parallel 98-element scan (1 block, 128 threads)
__global__ void k_scan2() {
    __shared__ int ws[4];
    int t = threadIdx.x;
    int lane = t & 31, wid = t >> 5;
    int v = (t < NB_SCAN) ? g_bsum[t] : 0;
    int s = v;
    #pragma unroll
    for (int off = 1; off < 32; off <<= 1) {
        int u = __shfl_up_sync(0xffffffffu, s, off);
        if (lane >= off) s += u;
    }
    if (lane == 31) ws[wid] = s;
    __syncthreads();
    int add = 0;
    #pragma unroll
    for (int w = 0; w < 4; w++) add += (w < wid) ? ws[w] : 0;
    if (t < NB_SCAN) g_bsum[t] = s + add - v;   // exclusive
}

__global__ void k_scan3() {
    int i = blockIdx.x * 256 + threadIdx.x;
    if (i >= NN) return;
    int rs = g_rs[i] + g_bsum[i >> 10];
    g_rs[i] = rs;
    g_cur[i] = rs;
    float c = (float)g_cnt[i];
    g_rinv1[i] = 1.f / (c + 1.f);
    g_rinv2[i] = 1.f / fmaxf(c, 1.f);
}

__global__ void k_fill(const int* __restrict__ src, const int* __restrict__ dst) {
    int e = blockIdx.x * 256 + threadIdx.x;
    if (e >= EE) return;
    int d = __ldg(dst + e);
    int pos = atomicAdd(&g_cur[d], 1);
    g_csr[pos] = __ldg(src + e);
}

// ---------------------------------------------------------------------------
// Aggregation 1: warp per node. g_hin[i] = (x_i + sum_j x_j)/(deg+1)
// ---------------------------------------------------------------------------
__global__ __launch_bounds__(256) void k_agg1(const float* __restrict__ x) {
    int w = blockIdx.x * 8 + (threadIdx.x >> 5);
    if (w >= NN) return;
    int lane = threadIdx.x & 31;
    int beg = __ldg(g_rs + w);
    int cnt = __ldg(g_cnt + w);
    float rinv = __ldg(g_rinv1 + w);

    float4 acc = *(const float4*)(x + (size_t)w * 128 + lane * 4);
    int j = 0;
    for (; j + 4 <= cnt; j += 4) {
        int s0 = __ldg(g_csr + beg + j);
        int s1 = __ldg(g_csr + beg + j + 1);
        int s2 = __ldg(g_csr + beg + j + 2);
        int s3 = __ldg(g_csr + beg + j + 3);
        float4 v0 = *(const float4*)(x + (size_t)s0 * 128 + lane * 4);
        float4 v1 = *(const float4*)(x + (size_t)s1 * 128 + lane * 4);
        float4 v2 = *(const float4*)(x + (size_t)s2 * 128 + lane * 4);
        float4 v3 = *(const float4*)(x + (size_t)s3 * 128 + lane * 4);
        acc.x += (v0.x + v1.x) + (v2.x + v3.x);
        acc.y += (v0.y + v1.y) + (v2.y + v3.y);
        acc.z += (v0.z + v1.z) + (v2.z + v3.z);
        acc.w += (v0.w + v1.w) + (v2.w + v3.w);
    }
    for (; j < cnt; j++) {
        int s0 = __ldg(g_csr + beg + j);
        float4 v0 = *(const float4*)(x + (size_t)s0 * 128 + lane * 4);
        acc.x += v0.x; acc.y += v0.y; acc.z += v0.z; acc.w += v0.w;
    }
    acc.x *= rinv; acc.y *= rinv; acc.z *= rinv; acc.w *= rinv;
    *((float4*)(g_hin + (size_t)w * 128 + lane * 4)) = acc;
}

// ---------------------------------------------------------------------------
// GEMM: 64 nodes x 128 cols per block, 256 threads, 8 rows x 4 cols/thread.
// A selected INSIDE device code from MODE (never pass __device__ globals as
// host-side kernel args — that was the 128MiB-delta bug).
// MODE 0: h = relu(g_hin @ W1 + b1)           -> g_h
// MODE 1: [z | y2] = g_h @ [W2s | W2n] (+b2)  -> g_z, g_y2
// ---------------------------------------------------------------------------
#define AS_STRIDE 68
#define SMEM_GEMM ((16384 + 128 * AS_STRIDE) * 4)

template <int MODE>
__global__ __launch_bounds__(256, 2) void k_gemm(const float* __restrict__ Wa,
                                                 const float* __restrict__ Wb,
                                                 const float* __restrict__ bias) {
    extern __shared__ float sm[];
    float* Ws = sm;            // [k][col] 128x128
    float* As = sm + 16384;    // [k][n]   128x68(pad)

    const float* A = (MODE == 0) ? g_hin : g_h;   // device-side symbol ref

    int tid = threadIdx.x;
    int n0 = blockIdx.x * 64;

    // Load W (MODE1 packs [W2s | W2n])
    for (int i = tid; i < 4096; i += 256) {
        float4 v;
        if (MODE == 0) {
            v = ((const float4*)Wa)[i];
        } else {
            int k = i >> 5, c4 = i & 31;
            v = (c4 < 16) ? ((const float4*)(Wa + k * 64))[c4]
                          : ((const float4*)(Wb + k * 64))[c4 - 16];
        }
        ((float4*)Ws)[i] = v;
    }

    // Load A tile, transposed into As[k][n]
    for (int i = tid; i < 2048; i += 256) {
        int n = i & 63, k4 = i >> 6;
        int gn = n0 + n;
        float4 v = make_float4(0.f, 0.f, 0.f, 0.f);
        if (gn < NN) v = ((const float4*)(A + (size_t)gn * 128))[k4];
        As[(k4 * 4 + 0) * AS_STRIDE + n] = v.x;
        As[(k4 * 4 + 1) * AS_STRIDE + n] = v.y;
        As[(k4 * 4 + 2) * AS_STRIDE + n] = v.z;
        As[(k4 * 4 + 3) * AS_STRIDE + n] = v.w;
    }
    __syncthreads();

    int tx = tid & 31, ty = tid >> 5;   // tx: 32 col-groups(x4), ty: 8 row-groups(x8)

    float acc[8][4];
    #pragma unroll
    for (int i = 0; i < 8; i++)
        #pragma unroll
        for (int j = 0; j < 4; j++) acc[i][j] = 0.f;

    const float* A0 = As + ty * 8;
    const float* B0 = Ws + tx * 4;

    #pragma unroll 4
    for (int k = 0; k < 128; k++) {
        float4 a0 = *(const float4*)(A0 + k * AS_STRIDE);
        float4 a1 = *(const float4*)(A0 + k * AS_STRIDE + 4);
        float4 b0 = *(const float4*)(B0 + k * 128);
        float aa[8] = {a0.x, a0.y, a0.z, a0.w, a1.x, a1.y, a1.z, a1.w};
        #pragma unroll
        for (int i = 0; i < 8; i++) {
            acc[i][0] = fmaf(aa[i], b0.x, acc[i][0]);
            acc[i][1] = fmaf(aa[i], b0.y, acc[i][1]);
            acc[i][2] = fmaf(aa[i], b0.z, acc[i][2]);
            acc[i][3] = fmaf(aa[i], b0.w, acc[i][3]);
        }
    }

    if (MODE == 0) {
        float b0 = __ldg(bias + tx * 4 + 0);
        float b1 = __ldg(bias + tx * 4 + 1);
        float b2 = __ldg(bias + tx * 4 + 2);
        float b3 = __ldg(bias + tx * 4 + 3);
        #pragma unroll
        for (int i = 0; i < 8; i++) {
            int gn = n0 + ty * 8 + i;
            if (gn < NN) {
                float4 o;
                o.x = fmaxf(acc[i][0] + b0, 0.f);
                o.y = fmaxf(acc[i][1] + b1, 0.f);
                o.z = fmaxf(acc[i][2] + b2, 0.f);
                o.w = fmaxf(acc[i][3] + b3, 0.f);
                *((float4*)(g_h + (size_t)gn * 128 + tx * 4)) = o;
            }
        }
    } else {
        bool isZ = (tx < 16);
        float b0 = isZ ? __ldg(bias + tx * 4 + 0) : 0.f;
        float b1 = isZ ? __ldg(bias + tx * 4 + 1) : 0.f;
        float b2 = isZ ? __ldg(bias + tx * 4 + 2) : 0.f;
        float b3 = isZ ? __ldg(bias + tx * 4 + 3) : 0.f;
        float* outp = isZ ? g_z : g_y2;
        int cbase = isZ ? tx * 4 : (tx - 16) * 4;
        #pragma unroll
        for (int i = 0; i < 8; i++) {
            int gn = n0 + ty * 8 + i;
            if (gn < NN) {
                float4 o;
                o.x = acc[i][0] + b0;
                o.y = acc[i][1] + b1;
                o.z = acc[i][2] + b2;
                o.w = acc[i][3] + b3;
                *((float4*)(outp + (size_t)gn * 64 + cbase)) = o;
            }
        }
    }
}

// ---------------------------------------------------------------------------
// Aggregation 2 + epilogue: out = z + (sum_j y2_j) * rinv2
// Half-warp per node: 16 lanes x float4 = 64 floats per row.
// ---------------------------------------------------------------------------
__global__ __launch_bounds__(256) void k_agg2out(float* __restrict__ out) {
    int w = blockIdx.x * 16 + (threadIdx.x >> 4);
    if (w >= NN) return;
    int lane = threadIdx.x & 15;
    int beg = __ldg(g_rs + w);
    int cnt = __ldg(g_cnt + w);
    float rinv = __ldg(g_rinv2 + w);

    float4 acc = make_float4(0.f, 0.f, 0.f, 0.f);
    int j = 0;
    for (; j + 4 <= cnt; j += 4) {
        int s0 = __ldg(g_csr + beg + j);
        int s1 = __ldg(g_csr + beg + j + 1);
        int s2 = __ldg(g_csr + beg + j + 2);
        int s3 = __ldg(g_csr + beg + j + 3);
        float4 v0 = *(const float4*)(g_y2 + (size_t)s0 * 64 + lane * 4);
        float4 v1 = *(const float4*)(g_y2 + (size_t)s1 * 64 + lane * 4);
        float4 v2 = *(const float4*)(g_y2 + (size_t)s2 * 64 + lane * 4);
        float4 v3 = *(const float4*)(g_y2 + (size_t)s3 * 64 + lane * 4);
        acc.x += (v0.x + v1.x) + (v2.x + v3.x);
        acc.y += (v0.y + v1.y) + (v2.y + v3.y);
        acc.z += (v0.z + v1.z) + (v2.z + v3.z);
        acc.w += (v0.w + v1.w) + (v2.w + v3.w);
    }
    for (; j < cnt; j++) {
        int s0 = __ldg(g_csr + beg + j);
        float4 v0 = *(const float4*)(g_y2 + (size_t)s0 * 64 + lane * 4);
        acc.x += v0.x; acc.y += v0.y; acc.z += v0.z; acc.w += v0.w;
    }
    float4 z = *(const float4*)(g_z + (size_t)w * 64 + lane * 4);
    float4 o;
    o.x = z.x + acc.x * rinv;
    o.y = z.y + acc.y * rinv;
    o.z = z.z + acc.z * rinv;
    o.w = z.w + acc.w * rinv;
    *((float4*)(out + (size_t)w * 64 + lane * 4)) = o;
}

// ---------------------------------------------------------------------------
extern "C" void kernel_launch(void* const* d_in, const int* in_sizes, int n_in,
                              void* d_out, int out_size) {
    const float* x   = (const float*)d_in[0];
    const float* W1  = (const float*)d_in[1];
    const float* b1  = (const float*)d_in[2];
    const float* W2n = (const float*)d_in[3];
    const float* W2s = (const float*)d_in[4];
    const float* b2  = (const float*)d_in[5];
    const int*   ei  = (const int*)d_in[6];
    const int* src = ei;
    const int* dst = ei + EE;

    cudaFuncSetAttribute(k_gemm<0>, cudaFuncAttributeMaxDynamicSharedMemorySize, SMEM_GEMM);
    cudaFuncSetAttribute(k_gemm<1>, cudaFuncAttributeMaxDynamicSharedMemorySize, SMEM_GEMM);

    // CSR build
    k_zero<<<(NN + 255) / 256, 256>>>();
    k_hist<<<(EE + 255) / 256, 256>>>(dst);
    k_scan1<<<NB_SCAN, 1024>>>();
    k_scan2<<<1, 128>>>();
    k_scan3<<<(NN + 255) / 256, 256>>>();
    k_fill<<<(EE + 255) / 256, 256>>>(src, dst);

    // Layer 1
    k_agg1<<<(NN + 7) / 8, 256>>>(x);
    k_gemm<0><<<(NN + 63) / 64, 256, SMEM_GEMM>>>(W1, nullptr, b1);

    // Layer 2
    k_gemm<1><<<(NN + 63) / 64, 256, SMEM_GEMM>>>(W2s, W2n, b2);
    k_agg2out<<<(NN + 15) / 16, 256>>>((float*)d_out);
}

// round 8
// speedup vs baseline: 2.0328x; 1.1187x over previous
#include <cuda_runtime.h>
#include <cstdint>

#define NN 100000
#define EE 1600000
#define NB_SCAN 98   // ceil(NN/1024)

// ---------------- scratch (__device__ globals; no allocation allowed) ------
// NOTE: never pass these as host-side kernel arguments (host shadow symbol !=
// device address; caused the 128MiB-delta guard trips in R3-R6). Reference
// them inside device code only.
__device__ int   g_cnt[NN];
__device__ int   g_rs[NN];
__device__ int   g_cur[NN];
__device__ int   g_bsum[NB_SCAN];
__device__ float g_rinv1[NN];
__device__ float g_rinv2[NN];
__device__ int   g_csr[EE];
__device__ float g_hin[(size_t)NN * 128];
__device__ float g_h[(size_t)NN * 128];
__device__ float g_y2[(size_t)NN * 64];
__device__ float g_z[(size_t)NN * 64];

// ---------------------------------------------------------------------------
// CSR build
// ---------------------------------------------------------------------------
__global__ void k_zero() {
    int i = blockIdx.x * 256 + threadIdx.x;
    if (i < NN) g_cnt[i] = 0;
}

__global__ void k_hist(const int* __restrict__ dst) {
    int e = blockIdx.x * 256 + threadIdx.x;
    if (e < EE) atomicAdd(&g_cnt[__ldg(dst + e)], 1);
}

__global__ void k_scan1() {
    __shared__ int s[1024];
    int t = threadIdx.x;
    int i = blockIdx.x * 1024 + t;
    int v = (i < NN) ? g_cnt[i] : 0;
    s[t] = v;
    __syncthreads();
    #pragma unroll
    for (int off = 1; off < 1024; off <<= 1) {
        int u = (t >= off) ? s[t - off] : 0;
        __syncthreads();
        s[t] += u;
        __syncthreads();
    }
    if (i < NN) g_rs[i] = s[t] - v;
    if (t == 1023) g_bsum[blockIdx.x] = s[1023];
}

__global__ void k_scan2() {
    __shared__ int ws[4];
    int t = threadIdx.x;
    int lane = t & 31, wid = t >> 5;
    int v = (t < NB_SCAN) ? g_bsum[t] : 0;
    int s = v;
    #pragma unroll
    for (int off = 1; off < 32; off <<= 1) {
        int u = __shfl_up_sync(0xffffffffu, s, off);
        if (lane >= off) s += u;
    }
    if (lane == 31) ws[wid] = s;
    __syncthreads();
    int add = 0;
    #pragma unroll
    for (int w = 0; w < 4; w++) add += (w < wid) ? ws[w] : 0;
    if (t < NB_SCAN) g_bsum[t] = s + add - v;   // exclusive
}

__global__ void k_scan3() {
    int i = blockIdx.x * 256 + threadIdx.x;
    if (i >= NN) return;
    int rs = g_rs[i] + g_bsum[i >> 10];
    g_rs[i] = rs;
    g_cur[i] = rs;
    float c = (float)g_cnt[i];
    g_rinv1[i] = 1.f / (c + 1.f);
    g_rinv2[i] = 1.f / fmaxf(c, 1.f);
}

__global__ void k_fill(const int* __restrict__ src, const int* __restrict__ dst) {
    int e = blockIdx.x * 256 + threadIdx.x;
    if (e >= EE) return;
    int d = __ldg(dst + e);
    int pos = atomicAdd(&g_cur[d], 1);
    g_csr[pos] = __ldg(src + e);
}

// ---------------------------------------------------------------------------
// Aggregation 1: warp per node, unroll 8. g_hin[i] = (x_i + sum_j x_j)/(deg+1)
// ---------------------------------------------------------------------------
__global__ __launch_bounds__(256) void k_agg1(const float* __restrict__ x) {
    int w = blockIdx.x * 8 + (threadIdx.x >> 5);
    if (w >= NN) return;
    int lane = threadIdx.x & 31;
    int beg = __ldg(g_rs + w);
    int cnt = __ldg(g_cnt + w);
    float rinv = __ldg(g_rinv1 + w);

    float4 acc = *(const float4*)(x + (size_t)w * 128 + lane * 4);
    int j = 0;
    for (; j + 8 <= cnt; j += 8) {
        int sidx[8];
        #pragma unroll
        for (int u = 0; u < 8; u++) sidx[u] = __ldg(g_csr + beg + j + u);
        float4 v[8];
        #pragma unroll
        for (int u = 0; u < 8; u++)
            v[u] = *(const float4*)(x + (size_t)sidx[u] * 128 + lane * 4);
        #pragma unroll
        for (int u = 0; u < 8; u++) {
            acc.x += v[u].x; acc.y += v[u].y; acc.z += v[u].z; acc.w += v[u].w;
        }
    }
    for (; j < cnt; j++) {
        int s0 = __ldg(g_csr + beg + j);
        float4 v0 = *(const float4*)(x + (size_t)s0 * 128 + lane * 4);
        acc.x += v0.x; acc.y += v0.y; acc.z += v0.z; acc.w += v0.w;
    }
    acc.x *= rinv; acc.y *= rinv; acc.z *= rinv; acc.w *= rinv;
    *((float4*)(g_hin + (size_t)w * 128 + lane * 4)) = acc;
}

// ---------------------------------------------------------------------------
// GEMM: 64 nodes x 128 cols per block, 256 threads, 8 rows x 4 cols/thread.
// Inner product via packed fma.rn.f32x2; accumulators pair adjacent rows so
// A pairs load directly from As[k][n] as b64 (no packing); only the 4 B
// broadcasts are packed per k. 16x64-bit acc = 32 regs -> no spill.
// MODE 0: h = relu(g_hin @ W1 + b1)           -> g_h
// MODE 1: [z | y2] = g_h @ [W2s | W2n] (+b2)  -> g_z, g_y2
// ---------------------------------------------------------------------------
#define AS_STRIDE 68   // floats; 272 B row stride (16B-aligned)
#define SMEM_GEMM ((16384 + 128 * AS_STRIDE) * 4)

__device__ __forceinline__ unsigned long long pack2(float a) {
    unsigned long long d;
    unsigned int u = __float_as_uint(a);
    asm("mov.b64 %0, {%1,%1};" : "=l"(d) : "r"(u));
    return d;
}
#define FMA2(d, a, b) asm("fma.rn.f32x2 %0, %1, %2, %0;" : "+l"(d) : "l"(a), "l"(b))

template <int MODE>
__global__ __launch_bounds__(256, 2) void k_gemm(const float* __restrict__ Wa,
                                                 const float* __restrict__ Wb,
                                                 const float* __restrict__ bias) {
    extern __shared__ float sm[];
    float* Ws = sm;            // [k][col] 128x128
    float* As = sm + 16384;    // [k][n]   128x68(pad)

    const float* A = (MODE == 0) ? g_hin : g_h;   // device-side symbol refs

    int tid = threadIdx.x;
    int n0 = blockIdx.x * 64;

    // Load W (MODE1 packs [W2s | W2n])
    for (int i = tid; i < 4096; i += 256) {
        float4 v;
        if (MODE == 0) {
            v = ((const float4*)Wa)[i];
        } else {
            int k = i >> 5, c4 = i & 31;
            v = (c4 < 16) ? ((const float4*)(Wa + k * 64))[c4]
                          : ((const float4*)(Wb + k * 64))[c4 - 16];
        }
        ((float4*)Ws)[i] = v;
    }

    // Load A tile, transposed into As[k][n]
    for (int i = tid; i < 2048; i += 256) {
        int n = i & 63, k4 = i >> 6;
        int gn = n0 + n;
        float4 v = make_float4(0.f, 0.f, 0.f, 0.f);
        if (gn < NN) v = ((const float4*)(A + (size_t)gn * 128))[k4];
        As[(k4 * 4 + 0) * AS_STRIDE + n] = v.x;
        As[(k4 * 4 + 1) * AS_STRIDE + n] = v.y;
        As[(k4 * 4 + 2) * AS_STRIDE + n] = v.z;
        As[(k4 * 4 + 3) * AS_STRIDE + n] = v.w;
    }
    __syncthreads();

    int tx = tid & 31, ty = tid >> 5;

    // acc[p][j]: row pair (2p, 2p+1) x col j, packed f32x2
    unsigned long long acc[4][4];
    #pragma unroll
    for (int p = 0; p < 4; p++)
        #pragma unroll
        for (int j = 0; j < 4; j++) acc[p][j] = 0ull;

    uint32_t a_base = (uint32_t)__cvta_generic_to_shared(As) + ty * 32;
    const float* B0 = Ws + tx * 4;

    #pragma unroll 4
    for (int k = 0; k < 128; k++) {
        unsigned long long a01, a23, a45, a67;
        uint32_t aa = a_base + (uint32_t)k * (AS_STRIDE * 4);
        asm("ld.shared.v2.b64 {%0,%1}, [%2];" : "=l"(a01), "=l"(a23) : "r"(aa));
        asm("ld.shared.v2.b64 {%0,%1}, [%2];" : "=l"(a45), "=l"(a67) : "r"(aa + 16));
        float4 b = *(const float4*)(B0 + k * 128);
        unsigned long long bx = pack2(b.x), by = pack2(b.y),
                           bz = pack2(b.z), bw = pack2(b.w);
        FMA2(acc[0][0], a01, bx); FMA2(acc[0][1], a01, by);
        FMA2(acc[0][2], a01, bz); FMA2(acc[0][3], a01, bw);
        FMA2(acc[1][0], a23, bx); FMA2(acc[1][1], a23, by);
        FMA2(acc[1][2], a23, bz); FMA2(acc[1][3], a23, bw);
        FMA2(acc[2][0], a45, bx); FMA2(acc[2][1], a45, by);
        FMA2(acc[2][2], a45, bz); FMA2(acc[2][3], a45, bw);
        FMA2(acc[3][0], a67, bx); FMA2(acc[3][1], a67, by);
        FMA2(acc[3][2], a67, bz); FMA2(acc[3][3], a67, bw);
    }

    // Epilogue
    float b0c, b1c, b2c, b3c;
    float* outp;
    int cbase;
    if (MODE == 0) {
        b0c = __ldg(bias + tx * 4 + 0);
        b1c = __ldg(bias + tx * 4 + 1);
        b2c = __ldg(bias + tx * 4 + 2);
        b3c = __ldg(bias + tx * 4 + 3);
        outp = g_h; cbase = tx * 4;
    } else {
        bool isZ = (tx < 16);
        b0c = isZ ? __ldg(bias + tx * 4 + 0) : 0.f;
        b1c = isZ ? __ldg(bias + tx * 4 + 1) : 0.f;
        b2c = isZ ? __ldg(bias + tx * 4 + 2) : 0.f;
        b3c = isZ ? __ldg(bias + tx * 4 + 3) : 0.f;
        outp = isZ ? g_z : g_y2;
        cbase = isZ ? tx * 4 : (tx - 16) * 4;
    }
    const int rowStride = (MODE == 0) ? 128 : 64;

    #pragma unroll
    for (int p = 0; p < 4; p++) {
        float lo[4], hi[4];
        #pragma unroll
        for (int j = 0; j < 4; j++) {
            unsigned int l, h;
            asm("mov.b64 {%0,%1}, %2;" : "=r"(l), "=r"(h) : "l"(acc[p][j]));
            lo[j] = __uint_as_float(l);
            hi[j] = __uint_as_float(h);
        }
        int gn0 = n0 + ty * 8 + 2 * p;
        float4 oe, oo;
        oe.x = lo[0] + b0c; oe.y = lo[1] + b1c; oe.z = lo[2] + b2c; oe.w = lo[3] + b3c;
        oo.x = hi[0] + b0c; oo.y = hi[1] + b1c; oo.z = hi[2] + b2c; oo.w = hi[3] + b3c;
        if (MODE == 0) {
            oe.x = fmaxf(oe.x, 0.f); oe.y = fmaxf(oe.y, 0.f);
            oe.z = fmaxf(oe.z, 0.f); oe.w = fmaxf(oe.w, 0.f);
            oo.x = fmaxf(oo.x, 0.f); oo.y = fmaxf(oo.y, 0.f);
            oo.z = fmaxf(oo.z, 0.f); oo.w = fmaxf(oo.w, 0.f);
        }
        if (gn0 < NN)
            *((float4*)(outp + (size_t)gn0 * rowStride + cbase)) = oe;
        if (gn0 + 1 < NN)
            *((float4*)(outp + (size_t)(gn0 + 1) * rowStride + cbase)) = oo;
    }
}

// ---------------------------------------------------------------------------
// Aggregation 2 + epilogue: out = z + (sum_j y2_j) * rinv2
// Half-warp per node: 16 lanes x float4, unroll 8.
// ---------------------------------------------------------------------------
__global__ __launch_bounds__(256) void k_agg2out(float* __restrict__ out) {
    int w = blockIdx.x * 16 + (threadIdx.x >> 4);
    if (w >= NN) return;
    int lane = threadIdx.x & 15;
    int beg = __ldg(g_rs + w);
    int cnt = __ldg(g_cnt + w);
    float rinv = __ldg(g_rinv2 + w);

    float4 acc = make_float4(0.f, 0.f, 0.f, 0.f);
    int j = 0;
    for (; j + 8 <= cnt; j += 8) {
        int sidx[8];
        #pragma unroll
        for (int u = 0; u < 8; u++) sidx[u] = __ldg(g_csr + beg + j + u);
        float4 v[8];
        #pragma unroll
        for (int u = 0; u < 8; u++)
            v[u] = *(const float4*)(g_y2 + (size_t)sidx[u] * 64 + lane * 4);
        #pragma unroll
        for (int u = 0; u < 8; u++) {
            acc.x += v[u].x; acc.y += v[u].y; acc.z += v[u].z; acc.w += v[u].w;
        }
    }
    for (; j < cnt; j++) {
        int s0 = __ldg(g_csr + beg + j);
        float4 v0 = *(const float4*)(g_y2 + (size_t)s0 * 64 + lane * 4);
        acc.x += v0.x; acc.y += v0.y; acc.z += v0.z; acc.w += v0.w;
    }
    float4 z = *(const float4*)(g_z + (size_t)w * 64 + lane * 4);
    float4 o;
    o.x = z.x + acc.x * rinv;
    o.y = z.y + acc.y * rinv;
    o.z = z.z + acc.z * rinv;
    o.w = z.w + acc.w * rinv;
    *((float4*)(out + (size_t)w * 64 + lane * 4)) = o;
}

// ---------------------------------------------------------------------------
extern "C" void kernel_launch(void* const* d_in, const int* in_sizes, int n_in,
                              void* d_out, int out_size) {
    const float* x   = (const float*)d_in[0];
    const float* W1  = (const float*)d_in[1];
    const float* b1  = (const float*)d_in[2];
    const float* W2n = (const float*)d_in[3];
    const float* W2s = (const float*)d_in[4];
    const float* b2  = (const float*)d_in[5];
    const int*   ei  = (const int*)d_in[6];
    const int* src = ei;
    const int* dst = ei + EE;

    cudaFuncSetAttribute(k_gemm<0>, cudaFuncAttributeMaxDynamicSharedMemorySize, SMEM_GEMM);
    cudaFuncSetAttribute(k_gemm<1>, cudaFuncAttributeMaxDynamicSharedMemorySize, SMEM_GEMM);

    // CSR build
    k_zero<<<(NN + 255) / 256, 256>>>();
    k_hist<<<(EE + 255) / 256, 256>>>(dst);
    k_scan1<<<NB_SCAN, 1024>>>();
    k_scan2<<<1, 128>>>();
    k_scan3<<<(NN + 255) / 256, 256>>>();
    k_fill<<<(EE + 255) / 256, 256>>>(src, dst);

    // Layer 1
    k_agg1<<<(NN + 7) / 8, 256>>>(x);
    k_gemm<0><<<(NN + 63) / 64, 256, SMEM_GEMM>>>(W1, nullptr, b1);

    // Layer 2
    k_gemm<1><<<(NN + 63) / 64, 256, SMEM_GEMM>>>(W2s, W2n, b2);
    k_agg2out<<<(NN + 15) / 16, 256>>>((float*)d_out);
}

// round 9
// speedup vs baseline: 2.0682x; 1.0174x over previous
#include <cuda_runtime.h>
#include <cstdint>

#define NN 100000
#define EE 1600000
#define NB_SCAN 98          // ceil(NN/1024)
#define GEMM_BLOCKS 1563    // ceil(NN/64)
#define HIST_BLOCKS 64
#define GA 520              // gemm0 tiles merged with hist (M1)
#define GB (GEMM_BLOCKS - GA)
#define FILL_BLOCKS 128

// ---------------- scratch (__device__ globals; no allocation allowed) ------
// NOTE: never pass these as host-side kernel arguments (host shadow symbol !=
// device address; caused the 128MiB-delta guard trips in R3-R6). Reference
// them inside device code only.
__device__ int   g_cnt[NN];
__device__ int   g_rs[NN];
__device__ int   g_cur[NN];
__device__ int   g_bsum[NB_SCAN];
__device__ float g_rinv1[NN];
__device__ float g_rinv2[NN];
__device__ int   g_csr[EE];
__device__ float g_y1[(size_t)NN * 128];   // x @ W1 (pre-aggregation, layer 1)
__device__ float g_h[(size_t)NN * 128];    // hidden activations
__device__ float g_y2[(size_t)NN * 64];    // h @ W2n
__device__ float g_z[(size_t)NN * 64];     // h @ W2s + b2

// ---------------------------------------------------------------------------
// f32x2 helpers
// ---------------------------------------------------------------------------
__device__ __forceinline__ unsigned long long pack2(float a) {
    unsigned long long d;
    unsigned int u = __float_as_uint(a);
    asm("mov.b64 %0, {%1,%1};" : "=l"(d) : "r"(u));
    return d;
}
#define FMA2(d, a, b) asm("fma.rn.f32x2 %0, %1, %2, %0;" : "+l"(d) : "l"(a), "l"(b))

#define AS_STRIDE 68   // floats; 272 B row stride (16B-aligned)
#define SMEM_GEMM ((16384 + 128 * AS_STRIDE) * 4)

// ---------------------------------------------------------------------------
// gemm0 tile: y1[64 rows x 128 cols] = x_tile @ W1 (no bias/relu here).
// 256 threads, 8 rows x 4 cols per thread, row-pair f32x2 accumulators.
// ---------------------------------------------------------------------------
__device__ __forceinline__ void gemm0_tile(const float* __restrict__ x,
                                           const float* __restrict__ W1,
                                           int bid) {
    extern __shared__ float sm[];
    float* Ws = sm;            // [k][col] 128x128
    float* As = sm + 16384;    // [k][n]   128x68(pad)

    int tid = threadIdx.x;
    int n0 = bid * 64;

    for (int i = tid; i < 4096; i += 256)
        ((float4*)Ws)[i] = ((const float4*)W1)[i];

    for (int i = tid; i < 2048; i += 256) {
        int n = i & 63, k4 = i >> 6;
        int gn = n0 + n;
        float4 v = make_float4(0.f, 0.f, 0.f, 0.f);
        if (gn < NN) v = ((const float4*)(x + (size_t)gn * 128))[k4];
        As[(k4 * 4 + 0) * AS_STRIDE + n] = v.x;
        As[(k4 * 4 + 1) * AS_STRIDE + n] = v.y;
        As[(k4 * 4 + 2) * AS_STRIDE + n] = v.z;
        As[(k4 * 4 + 3) * AS_STRIDE + n] = v.w;
    }
    __syncthreads();

    int tx = tid & 31, ty = tid >> 5;

    unsigned long long acc[4][4];
    #pragma unroll
    for (int p = 0; p < 4; p++)
        #pragma unroll
        for (int j = 0; j < 4; j++) acc[p][j] = 0ull;

    uint32_t a_base = (uint32_t)__cvta_generic_to_shared(As) + ty * 32;
    const float* B0 = Ws + tx * 4;

    #pragma unroll 4
    for (int k = 0; k < 128; k++) {
        unsigned long long a01, a23, a45, a67;
        uint32_t aa = a_base + (uint32_t)k * (AS_STRIDE * 4);
        asm("ld.shared.v2.b64 {%0,%1}, [%2];" : "=l"(a01), "=l"(a23) : "r"(aa));
        asm("ld.shared.v2.b64 {%0,%1}, [%2];" : "=l"(a45), "=l"(a67) : "r"(aa + 16));
        float4 b = *(const float4*)(B0 + k * 128);
        unsigned long long bx = pack2(b.x), by = pack2(b.y),
                           bz = pack2(b.z), bw = pack2(b.w);
        FMA2(acc[0][0], a01, bx); FMA2(acc[0][1], a01, by);
        FMA2(acc[0][2], a01, bz); FMA2(acc[0][3], a01, bw);
        FMA2(acc[1][0], a23, bx); FMA2(acc[1][1], a23, by);
        FMA2(acc[1][2], a23, bz); FMA2(acc[1][3], a23, bw);
        FMA2(acc[2][0], a45, bx); FMA2(acc[2][1], a45, by);
        FMA2(acc[2][2], a45, bz); FMA2(acc[2][3], a45, bw);
        FMA2(acc[3][0], a67, bx); FMA2(acc[3][1], a67, by);
        FMA2(acc[3][2], a67, bz); FMA2(acc[3][3], a67, bw);
    }

    int cbase = tx * 4;
    #pragma unroll
    for (int p = 0; p < 4; p++) {
        float lo[4], hi[4];
        #pragma unroll
        for (int j = 0; j < 4; j++) {
            unsigned int l, h;
            asm("mov.b64 {%0,%1}, %2;" : "=r"(l), "=r"(h) : "l"(acc[p][j]));
            lo[j] = __uint_as_float(l);
            hi[j] = __uint_as_float(h);
        }
        int gn0 = n0 + ty * 8 + 2 * p;
        if (gn0 < NN)
            *((float4*)(g_y1 + (size_t)gn0 * 128 + cbase)) =
                make_float4(lo[0], lo[1], lo[2], lo[3]);
        if (gn0 + 1 < NN)
            *((float4*)(g_y1 + (size_t)(gn0 + 1) * 128 + cbase)) =
                make_float4(hi[0], hi[1], hi[2], hi[3]);
    }
}

// ---------------------------------------------------------------------------
// CSR build pieces
// ---------------------------------------------------------------------------
__global__ void k_zero() {
    int i = blockIdx.x * 256 + threadIdx.x;
    if (i < NN) g_cnt[i] = 0;
}

// M1: hist (blocks 0..HIST_BLOCKS-1, grid-stride) || gemm0 tiles [0, GA)
__global__ __launch_bounds__(256, 2) void k_m1(const float* __restrict__ x,
                                               const float* __restrict__ W1,
                                               const int* __restrict__ dst) {
    if (blockIdx.x < HIST_BLOCKS) {
        for (int e = blockIdx.x * 256 + threadIdx.x; e < EE; e += HIST_BLOCKS * 256)
            atomicAdd(&g_cnt[__ldg(dst + e)], 1);
        return;
    }
    gemm0_tile(x, W1, blockIdx.x - HIST_BLOCKS);
}

__global__ void k_scan1() {
    __shared__ int s[1024];
    int t = threadIdx.x;
    int i = blockIdx.x * 1024 + t;
    int v = (i < NN) ? g_cnt[i] : 0;
    s[t] = v;
    __syncthreads();
    #pragma unroll
    for (int off = 1; off < 1024; off <<= 1) {
        int u = (t >= off) ? s[t - off] : 0;
        __syncthreads();
        s[t] += u;
        __syncthreads();
    }
    if (i < NN) g_rs[i] = s[t] - v;
    if (t == 1023) g_bsum[blockIdx.x] = s[1023];
}

__global__ void k_scan2() {
    __shared__ int ws[4];
    int t = threadIdx.x;
    int lane = t & 31, wid = t >> 5;
    int v = (t < NB_SCAN) ? g_bsum[t] : 0;
    int s = v;
    #pragma unroll
    for (int off = 1; off < 32; off <<= 1) {
        int u = __shfl_up_sync(0xffffffffu, s, off);
        if (lane >= off) s += u;
    }
    if (lane == 31) ws[wid] = s;
    __syncthreads();
    int add = 0;
    #pragma unroll
    for (int w = 0; w < 4; w++) add += (w < wid) ? ws[w] : 0;
    if (t < NB_SCAN) g_bsum[t] = s + add - v;   // exclusive
}

__global__ void k_scan3() {
    int i = blockIdx.x * 256 + threadIdx.x;
    if (i >= NN) return;
    int rs = g_rs[i] + g_bsum[i >> 10];
    g_rs[i] = rs;
    g_cur[i] = rs;
    float c = (float)g_cnt[i];
    g_rinv1[i] = 1.f / (c + 1.f);
    g_rinv2[i] = 1.f / fmaxf(c, 1.f);
}

// M2: fill (blocks 0..FILL_BLOCKS-1, grid-stride) || gemm0 tiles [GA, 1563)
__global__ __launch_bounds__(256, 2) void k_m2(const float* __restrict__ x,
                                               const float* __restrict__ W1,
                                               const int* __restrict__ src,
                                               const int* __restrict__ dst) {
    if (blockIdx.x < FILL_BLOCKS) {
        for (int e = blockIdx.x * 256 + threadIdx.x; e < EE; e += FILL_BLOCKS * 256) {
            int d = __ldg(dst + e);
            int pos = atomicAdd(&g_cur[d], 1);
            g_csr[pos] = __ldg(src + e);
        }
        return;
    }
    gemm0_tile(x, W1, blockIdx.x - FILL_BLOCKS + GA);
}

// ---------------------------------------------------------------------------
// Aggregation 1 (post-GEMM): h_i = relu((y1_i + sum_j y1_j)*rinv1 + b1)
// Warp per node, unroll 8.
// ---------------------------------------------------------------------------
__global__ __launch_bounds__(256) void k_agg1b(const float* __restrict__ b1) {
    int w = blockIdx.x * 8 + (threadIdx.x >> 5);
    if (w >= NN) return;
    int lane = threadIdx.x & 31;
    int beg = __ldg(g_rs + w);
    int cnt = __ldg(g_cnt + w);
    float rinv = __ldg(g_rinv1 + w);

    float4 acc = *(const float4*)(g_y1 + (size_t)w * 128 + lane * 4);  // self
    int j = 0;
    for (; j + 8 <= cnt; j += 8) {
        int sidx[8];
        #pragma unroll
        for (int u = 0; u < 8; u++) sidx[u] = __ldg(g_csr + beg + j + u);
        float4 v[8];
        #pragma unroll
        for (int u = 0; u < 8; u++)
            v[u] = *(const float4*)(g_y1 + (size_t)sidx[u] * 128 + lane * 4);
        #pragma unroll
        for (int u = 0; u < 8; u++) {
            acc.x += v[u].x; acc.y += v[u].y; acc.z += v[u].z; acc.w += v[u].w;
        }
    }
    for (; j < cnt; j++) {
        int s0 = __ldg(g_csr + beg + j);
        float4 v0 = *(const float4*)(g_y1 + (size_t)s0 * 128 + lane * 4);
        acc.x += v0.x; acc.y += v0.y; acc.z += v0.z; acc.w += v0.w;
    }
    float4 bb = *(const float4*)(b1 + lane * 4);
    float4 o;
    o.x = fmaxf(acc.x * rinv + bb.x, 0.f);
    o.y = fmaxf(acc.y * rinv + bb.y, 0.f);
    o.z = fmaxf(acc.z * rinv + bb.z, 0.f);
    o.w = fmaxf(acc.w * rinv + bb.w, 0.f);
    *((float4*)(g_h + (size_t)w * 128 + lane * 4)) = o;
}

// ---------------------------------------------------------------------------
// Layer-2 GEMM: [z | y2] = g_h @ [W2s | W2n] (+b2 on z half)
// ---------------------------------------------------------------------------
__global__ __launch_bounds__(256, 2) void k_gemm1(const float* __restrict__ Wa,
                                                  const float* __restrict__ Wb,
                                                  const float* __restrict__ bias) {
    extern __shared__ float sm[];
    float* Ws = sm;            // [k][col] 128x128 = [W2s | W2n]
    float* As = sm + 16384;    // [k][n]   128x68(pad)

    int tid = threadIdx.x;
    int n0 = blockIdx.x * 64;

    for (int i = tid; i < 4096; i += 256) {
        int k = i >> 5, c4 = i & 31;
        float4 v = (c4 < 16) ? ((const float4*)(Wa + k * 64))[c4]
                             : ((const float4*)(Wb + k * 64))[c4 - 16];
        ((float4*)Ws)[i] = v;
    }

    for (int i = tid; i < 2048; i += 256) {
        int n = i & 63, k4 = i >> 6;
        int gn = n0 + n;
        float4 v = make_float4(0.f, 0.f, 0.f, 0.f);
        if (gn < NN) v = ((const float4*)(g_h + (size_t)gn * 128))[k4];
        As[(k4 * 4 + 0) * AS_STRIDE + n] = v.x;
        As[(k4 * 4 + 1) * AS_STRIDE + n] = v.y;
        As[(k4 * 4 + 2) * AS_STRIDE + n] = v.z;
        As[(k4 * 4 + 3) * AS_STRIDE + n] = v.w;
    }
    __syncthreads();

    int tx = tid & 31, ty = tid >> 5;

    unsigned long long acc[4][4];
    #pragma unroll
    for (int p = 0; p < 4; p++)
        #pragma unroll
        for (int j = 0; j < 4; j++) acc[p][j] = 0ull;

    uint32_t a_base = (uint32_t)__cvta_generic_to_shared(As) + ty * 32;
    const float* B0 = Ws + tx * 4;

    #pragma unroll 4
    for (int k = 0; k < 128; k++) {
        unsigned long long a01, a23, a45, a67;
        uint32_t aa = a_base + (uint32_t)k * (AS_STRIDE * 4);
        asm("ld.shared.v2.b64 {%0,%1}, [%2];" : "=l"(a01), "=l"(a23) : "r"(aa));
        asm("ld.shared.v2.b64 {%0,%1}, [%2];" : "=l"(a45), "=l"(a67) : "r"(aa + 16));
        float4 b = *(const float4*)(B0 + k * 128);
        unsigned long long bx = pack2(b.x), by = pack2(b.y),
                           bz = pack2(b.z), bw = pack2(b.w);
        FMA2(acc[0][0], a01, bx); FMA2(acc[0][1], a01, by);
        FMA2(acc[0][2], a01, bz); FMA2(acc[0][3], a01, bw);
        FMA2(acc[1][0], a23, bx); FMA2(acc[1][1], a23, by);
        FMA2(acc[1][2], a23, bz); FMA2(acc[1][3], a23, bw);
        FMA2(acc[2][0], a45, bx); FMA2(acc[2][1], a45, by);
        FMA2(acc[2][2], a45, bz); FMA2(acc[2][3], a45, bw);
        FMA2(acc[3][0], a67, bx); FMA2(acc[3][1], a67, by);
        FMA2(acc[3][2], a67, bz); FMA2(acc[3][3], a67, bw);
    }

    bool isZ = (tx < 16);
    float b0c = isZ ? __ldg(bias + tx * 4 + 0) : 0.f;
    float b1c = isZ ? __ldg(bias + tx * 4 + 1) : 0.f;
    float b2c = isZ ? __ldg(bias + tx * 4 + 2) : 0.f;
    float b3c = isZ ? __ldg(bias + tx * 4 + 3) : 0.f;
    float* outp = isZ ? g_z : g_y2;
    int cbase = isZ ? tx * 4 : (tx - 16) * 4;

    #pragma unroll
    for (int p = 0; p < 4; p++) {
        float lo[4], hi[4];
        #pragma unroll
        for (int j = 0; j < 4; j++) {
            unsigned int l, h;
            asm("mov.b64 {%0,%1}, %2;" : "=r"(l), "=r"(h) : "l"(acc[p][j]));
            lo[j] = __uint_as_float(l);
            hi[j] = __uint_as_float(h);
        }
        int gn0 = n0 + ty * 8 + 2 * p;
        if (gn0 < NN)
            *((float4*)(outp + (size_t)gn0 * 64 + cbase)) =
                make_float4(lo[0] + b0c, lo[1] + b1c, lo[2] + b2c, lo[3] + b3c);
        if (gn0 + 1 < NN)
            *((float4*)(outp + (size_t)(gn0 + 1) * 64 + cbase)) =
                make_float4(hi[0] + b0c, hi[1] + b1c, hi[2] + b2c, hi[3] + b3c);
    }
}

// ---------------------------------------------------------------------------
// Aggregation 2 + epilogue: out = z + (sum_j y2_j) * rinv2
// Half-warp per node: 16 lanes x float4, unroll 8.
// ---------------------------------------------------------------------------
__global__ __launch_bounds__(256) void k_agg2out(float* __restrict__ out) {
    int w = blockIdx.x * 16 + (threadIdx.x >> 4);
    if (w >= NN) return;
    int lane = threadIdx.x & 15;
    int beg = __ldg(g_rs + w);
    int cnt = __ldg(g_cnt + w);
    float rinv = __ldg(g_rinv2 + w);

    float4 acc = make_float4(0.f, 0.f, 0.f, 0.f);
    int j = 0;
    for (; j + 8 <= cnt; j += 8) {
        int sidx[8];
        #pragma unroll
        for (int u = 0; u < 8; u++) sidx[u] = __ldg(g_csr + beg + j + u);
        float4 v[8];
        #pragma unroll
        for (int u = 0; u < 8; u++)
            v[u] = *(const float4*)(g_y2 + (size_t)sidx[u] * 64 + lane * 4);
        #pragma unroll
        for (int u = 0; u < 8; u++) {
            acc.x += v[u].x; acc.y += v[u].y; acc.z += v[u].z; acc.w += v[u].w;
        }
    }
    for (; j < cnt; j++) {
        int s0 = __ldg(g_csr + beg + j);
        float4 v0 = *(const float4*)(g_y2 + (size_t)s0 * 64 + lane * 4);
        acc.x += v0.x; acc.y += v0.y; acc.z += v0.z; acc.w += v0.w;
    }
    float4 z = *(const float4*)(g_z + (size_t)w * 64 + lane * 4);
    float4 o;
    o.x = z.x + acc.x * rinv;
    o.y = z.y + acc.y * rinv;
    o.z = z.z + acc.z * rinv;
    o.w = z.w + acc.w * rinv;
    *((float4*)(out + (size_t)w * 64 + lane * 4)) = o;
}

// ---------------------------------------------------------------------------
extern "C" void kernel_launch(void* const* d_in, const int* in_sizes, int n_in,
                              void* d_out, int out_size) {
    const float* x   = (const float*)d_in[0];
    const float* W1  = (const float*)d_in[1];
    const float* b1  = (const float*)d_in[2];
    const float* W2n = (const float*)d_in[3];
    const float* W2s = (const float*)d_in[4];
    const float* b2  = (const float*)d_in[5];
    const int*   ei  = (const int*)d_in[6];
    const int* src = ei;
    const int* dst = ei + EE;

    cudaFuncSetAttribute(k_m1, cudaFuncAttributeMaxDynamicSharedMemorySize, SMEM_GEMM);
    cudaFuncSetAttribute(k_m2, cudaFuncAttributeMaxDynamicSharedMemorySize, SMEM_GEMM);
    cudaFuncSetAttribute(k_gemm1, cudaFuncAttributeMaxDynamicSharedMemorySize, SMEM_GEMM);

    k_zero<<<(NN + 255) / 256, 256>>>();
    k_m1<<<HIST_BLOCKS + GA, 256, SMEM_GEMM>>>(x, W1, dst);       // hist || gemm0 A
    k_scan1<<<NB_SCAN, 1024>>>();
    k_scan2<<<1, 128>>>();
    k_scan3<<<(NN + 255) / 256, 256>>>();
    k_m2<<<FILL_BLOCKS + GB, 256, SMEM_GEMM>>>(x, W1, src, dst);  // fill || gemm0 B
    k_agg1b<<<(NN + 7) / 8, 256>>>(b1);
    k_gemm1<<<(NN + 63) / 64, 256, SMEM_GEMM>>>(W2s, W2n, b2);
    k_agg2out<<<(NN + 15) / 16, 256>>>((float*)d_out);
}

// round 11
// speedup vs baseline: 2.1538x; 1.0414x over previous
#include <cuda_runtime.h>
#include <cuda_fp16.h>
#include <cstdint>

#define NN 100000
#define EE 1600000
#define NB_SCAN 98          // ceil(NN/1024)
#define GEMM_BLOCKS 1563    // ceil(NN/64)
#define HIST_BLOCKS 64
#define GA 520              // gemm0 tiles merged with hist (M1)
#define GB (GEMM_BLOCKS - GA)
#define FILL_BLOCKS 128

// ---------------- scratch (__device__ globals; no allocation allowed) ------
// NOTE: never pass these as host-side kernel arguments (host shadow symbol !=
// device address; caused the 128MiB-delta guard trips in R3-R6).
__device__ int    g_cnt[NN];
__device__ int    g_rs[NN];
__device__ int    g_cur[NN];
__device__ int    g_bsum[NB_SCAN];
__device__ float  g_rinv1[NN];
__device__ float  g_rinv2[NN];
__device__ int    g_csr[EE];
__device__ float  g_y1[(size_t)NN * 128];    // x @ W1 (fp32)
__device__ __half g_y1h[(size_t)NN * 128];   // fp16 shadow for gather
__device__ float  g_h[(size_t)NN * 128];     // hidden activations
__device__ __half g_y2h[(size_t)NN * 64];    // h @ W2n (fp16, gather-only)
__device__ float  g_z[(size_t)NN * 64];      // h @ W2s + b2

// ---------------------------------------------------------------------------
// f32x2 helpers
// ---------------------------------------------------------------------------
__device__ __forceinline__ unsigned long long pack2(float a) {
    unsigned long long d;
    unsigned int u = __float_as_uint(a);
    asm("mov.b64 %0, {%1,%1};" : "=l"(d) : "r"(u));
    return d;
}
#define FMA2(d, a, b) asm("fma.rn.f32x2 %0, %1, %2, %0;" : "+l"(d) : "l"(a), "l"(b))

#define AS_STRIDE 68   // floats; 272 B row stride (16B-aligned)
#define SMEM_GEMM ((16384 + 128 * AS_STRIDE) * 4)

// half helpers
__device__ __forceinline__ unsigned int h2u(float a, float b) {
    __half2 h = __float22half2_rn(make_float2(a, b));
    return *(unsigned int*)&h;
}
__device__ __forceinline__ void h2acc(unsigned int u, float& a, float& b) {
    __half2 h = *(__half2*)&u;
    float2 f = __half22float2(h);
    a += f.x; b += f.y;
}

// ---------------------------------------------------------------------------
// gemm0 tile: y1[64 x 128] = x_tile @ W1 (fp32 + fp16 shadow stores).
// ---------------------------------------------------------------------------
__device__ __forceinline__ void gemm0_tile(const float* __restrict__ x,
                                           const float* __restrict__ W1,
                                           int bid) {
    extern __shared__ float sm[];
    float* Ws = sm;            // [k][col] 128x128
    float* As = sm + 16384;    // [k][n]   128x68(pad)

    int tid = threadIdx.x;
    int n0 = bid * 64;

    for (int i = tid; i < 4096; i += 256)
        ((float4*)Ws)[i] = ((const float4*)W1)[i];

    for (int i = tid; i < 2048; i += 256) {
        int n = i & 63, k4 = i >> 6;
        int gn = n0 + n;
        float4 v = make_float4(0.f, 0.f, 0.f, 0.f);
        if (gn < NN) v = ((const float4*)(x + (size_t)gn * 128))[k4];
        As[(k4 * 4 + 0) * AS_STRIDE + n] = v.x;
        As[(k4 * 4 + 1) * AS_STRIDE + n] = v.y;
        As[(k4 * 4 + 2) * AS_STRIDE + n] = v.z;
        As[(k4 * 4 + 3) * AS_STRIDE + n] = v.w;
    }
    __syncthreads();

    int tx = tid & 31, ty = tid >> 5;

    unsigned long long acc[4][4];
    #pragma unroll
    for (int p = 0; p < 4; p++)
        #pragma unroll
        for (int j = 0; j < 4; j++) acc[p][j] = 0ull;

    uint32_t a_base = (uint32_t)__cvta_generic_to_shared(As) + ty * 32;
    const float* B0 = Ws + tx * 4;

    #pragma unroll 4
    for (int k = 0; k < 128; k++) {
        unsigned long long a01, a23, a45, a67;
        uint32_t aa = a_base + (uint32_t)k * (AS_STRIDE * 4);
        asm("ld.shared.v2.b64 {%0,%1}, [%2];" : "=l"(a01), "=l"(a23) : "r"(aa));
        asm("ld.shared.v2.b64 {%0,%1}, [%2];" : "=l"(a45), "=l"(a67) : "r"(aa + 16));
        float4 b = *(const float4*)(B0 + k * 128);
        unsigned long long bx = pack2(b.x), by = pack2(b.y),
                           bz = pack2(b.z), bw = pack2(b.w);
        FMA2(acc[0][0], a01, bx); FMA2(acc[0][1], a01, by);
        FMA2(acc[0][2], a01, bz); FMA2(acc[0][3], a01, bw);
        FMA2(acc[1][0], a23, bx); FMA2(acc[1][1], a23, by);
        FMA2(acc[1][2], a23, bz); FMA2(acc[1][3], a23, bw);
        FMA2(acc[2][0], a45, bx); FMA2(acc[2][1], a45, by);
        FMA2(acc[2][2], a45, bz); FMA2(acc[2][3], a45, bw);
        FMA2(acc[3][0], a67, bx); FMA2(acc[3][1], a67, by);
        FMA2(acc[3][2], a67, bz); FMA2(acc[3][3], a67, bw);
    }

    int cbase = tx * 4;
    #pragma unroll
    for (int p = 0; p < 4; p++) {
        float lo[4], hi[4];
        #pragma unroll
        for (int j = 0; j < 4; j++) {
            unsigned int l, h;
            asm("mov.b64 {%0,%1}, %2;" : "=r"(l), "=r"(h) : "l"(acc[p][j]));
            lo[j] = __uint_as_float(l);
            hi[j] = __uint_as_float(h);
        }
        int gn0 = n0 + ty * 8 + 2 * p;
        if (gn0 < NN) {
            *((float4*)(g_y1 + (size_t)gn0 * 128 + cbase)) =
                make_float4(lo[0], lo[1], lo[2], lo[3]);
            *((uint2*)(g_y1h + (size_t)gn0 * 128 + cbase)) =
                make_uint2(h2u(lo[0], lo[1]), h2u(lo[2], lo[3]));
        }
        if (gn0 + 1 < NN) {
            *((float4*)(g_y1 + (size_t)(gn0 + 1) * 128 + cbase)) =
                make_float4(hi[0], hi[1], hi[2], hi[3]);
            *((uint2*)(g_y1h + (size_t)(gn0 + 1) * 128 + cbase)) =
                make_uint2(h2u(hi[0], hi[1]), h2u(hi[2], hi[3]));
        }
    }
}

// ---------------------------------------------------------------------------
// CSR build pieces
// ---------------------------------------------------------------------------
__global__ void k_zero() {
    int i = blockIdx.x * 256 + threadIdx.x;
    if (i < NN) g_cnt[i] = 0;
}

// M1: hist || gemm0 tiles [0, GA)
__global__ __launch_bounds__(256, 2) void k_m1(const float* __restrict__ x,
                                               const float* __restrict__ W1,
                                               const int* __restrict__ dst) {
    if (blockIdx.x < HIST_BLOCKS) {
        for (int e = blockIdx.x * 256 + threadIdx.x; e < EE; e += HIST_BLOCKS * 256)
            atomicAdd(&g_cnt[__ldg(dst + e)], 1);
        return;
    }
    gemm0_tile(x, W1, blockIdx.x - HIST_BLOCKS);
}

__global__ void k_scan1() {
    __shared__ int s[1024];
    int t = threadIdx.x;
    int i = blockIdx.x * 1024 + t;
    int v = (i < NN) ? g_cnt[i] : 0;
    s[t] = v;
    __syncthreads();
    #pragma unroll
    for (int off = 1; off < 1024; off <<= 1) {
        int u = (t >= off) ? s[t - off] : 0;
        __syncthreads();
        s[t] += u;
        __syncthreads();
    }
    if (i < NN) g_rs[i] = s[t] - v;
    if (t == 1023) g_bsum[blockIdx.x] = s[1023];
}

// scan3 with the 98-element block-sum scan inlined (replaces k_scan2 launch)
__global__ void k_scan3() {
    __shared__ int ws[4];
    __shared__ int sbs[NB_SCAN];
    int t = threadIdx.x;
    int lane = t & 31, wid = t >> 5;
    int v = 0, s = 0;
    if (t < 128) {
        v = (t < NB_SCAN) ? g_bsum[t] : 0;
        s = v;
        #pragma unroll
        for (int off = 1; off < 32; off <<= 1) {
            int u = __shfl_up_sync(0xffffffffu, s, off);
            if (lane >= off) s += u;
        }
        if (lane == 31) ws[wid] = s;
    }
    __syncthreads();
    if (t < NB_SCAN) {
        int add = 0;
        #pragma unroll
        for (int w = 0; w < 4; w++) add += (w < wid) ? ws[w] : 0;
        sbs[t] = s + add - v;   // exclusive prefix of block sums
    }
    __syncthreads();
    int i = blockIdx.x * 256 + t;
    if (i >= NN) return;
    int rs = g_rs[i] + sbs[i >> 10];
    g_rs[i] = rs;
    g_cur[i] = rs;
    float c = (float)g_cnt[i];
    g_rinv1[i] = 1.f / (c + 1.f);
    g_rinv2[i] = 1.f / fmaxf(c, 1.f);
}

// M2: fill || gemm0 tiles [GA, 1563)
__global__ __launch_bounds__(256, 2) void k_m2(const float* __restrict__ x,
                                               const float* __restrict__ W1,
                                               const int* __restrict__ src,
                                               const int* __restrict__ dst) {
    if (blockIdx.x < FILL_BLOCKS) {
        for (int e = blockIdx.x * 256 + threadIdx.x; e < EE; e += FILL_BLOCKS * 256) {
            int d = __ldg(dst + e);
            int pos = atomicAdd(&g_cur[d], 1);
            g_csr[pos] = __ldg(src + e);
        }
        return;
    }
    gemm0_tile(x, W1, blockIdx.x - FILL_BLOCKS + GA);
}

// ---------------------------------------------------------------------------
// Aggregation 1: h_i = relu((y1_i + sum_j y1h_j)*rinv1 + b1)
// Half-warp per node: 16 lanes x 8 cols; neighbors gathered fp16 (16B/lane).
// ---------------------------------------------------------------------------
__global__ __launch_bounds__(256) void k_agg1b(const float* __restrict__ b1) {
    int w = blockIdx.x * 16 + (threadIdx.x >> 4);
    if (w >= NN) return;
    int lane = threadIdx.x & 15;
    int beg = __ldg(g_rs + w);
    int cnt = __ldg(g_cnt + w);
    float rinv = __ldg(g_rinv1 + w);

    // self (fp32)
    float4 s0 = *(const float4*)(g_y1 + (size_t)w * 128 + lane * 8);
    float4 s1 = *(const float4*)(g_y1 + (size_t)w * 128 + lane * 8 + 4);
    float acc[8] = {s0.x, s0.y, s0.z, s0.w, s1.x, s1.y, s1.z, s1.w};

    int j = 0;
    for (; j + 8 <= cnt; j += 8) {
        int sidx[8];
        #pragma unroll
        for (int u = 0; u < 8; u++) sidx[u] = __ldg(g_csr + beg + j + u);
        uint4 r[8];
        #pragma unroll
        for (int u = 0; u < 8; u++)
            r[u] = *(const uint4*)(g_y1h + (size_t)sidx[u] * 128 + lane * 8);
        #pragma unroll
        for (int u = 0; u < 8; u++) {
            h2acc(r[u].x, acc[0], acc[1]);
            h2acc(r[u].y, acc[2], acc[3]);
            h2acc(r[u].z, acc[4], acc[5]);
            h2acc(r[u].w, acc[6], acc[7]);
        }
    }
    for (; j < cnt; j++) {
        int s = __ldg(g_csr + beg + j);
        uint4 r = *(const uint4*)(g_y1h + (size_t)s * 128 + lane * 8);
        h2acc(r.x, acc[0], acc[1]);
        h2acc(r.y, acc[2], acc[3]);
        h2acc(r.z, acc[4], acc[5]);
        h2acc(r.w, acc[6], acc[7]);
    }

    float4 bb0 = *(const float4*)(b1 + lane * 8);
    float4 bb1 = *(const float4*)(b1 + lane * 8 + 4);
    float4 o0, o1;
    o0.x = fmaxf(acc[0] * rinv + bb0.x, 0.f);
    o0.y = fmaxf(acc[1] * rinv + bb0.y, 0.f);
    o0.z = fmaxf(acc[2] * rinv + bb0.z, 0.f);
    o0.w = fmaxf(acc[3] * rinv + bb0.w, 0.f);
    o1.x = fmaxf(acc[4] * rinv + bb1.x, 0.f);
    o1.y = fmaxf(acc[5] * rinv + bb1.y, 0.f);
    o1.z = fmaxf(acc[6] * rinv + bb1.z, 0.f);
    o1.w = fmaxf(acc[7] * rinv + bb1.w, 0.f);
    *((float4*)(g_h + (size_t)w * 128 + lane * 8)) = o0;
    *((float4*)(g_h + (size_t)w * 128 + lane * 8 + 4)) = o1;
}

// ---------------------------------------------------------------------------
// Layer-2 GEMM: z(fp32,+b2) = h@W2s ; y2h(fp16) = h@W2n
// ---------------------------------------------------------------------------
__global__ __launch_bounds__(256, 2) void k_gemm1(const float* __restrict__ Wa,
                                                  const float* __restrict__ Wb,
                                                  const float* __restrict__ bias) {
    extern __shared__ float sm[];
    float* Ws = sm;            // [k][col] 128x128 = [W2s | W2n]
    float* As = sm + 16384;    // [k][n]   128x68(pad)

    int tid = threadIdx.x;
    int n0 = blockIdx.x * 64;

    for (int i = tid; i < 4096; i += 256) {
        int k = i >> 5, c4 = i & 31;
        float4 v = (c4 < 16) ? ((const float4*)(Wa + k * 64))[c4]
                             : ((const float4*)(Wb + k * 64))[c4 - 16];
        ((float4*)Ws)[i] = v;
    }

    for (int i = tid; i < 2048; i += 256) {
        int n = i & 63, k4 = i >> 6;
        int gn = n0 + n;
        float4 v = make_float4(0.f, 0.f, 0.f, 0.f);
        if (gn < NN) v = ((const float4*)(g_h + (size_t)gn * 128))[k4];
        As[(k4 * 4 + 0) * AS_STRIDE + n] = v.x;
        As[(k4 * 4 + 1) * AS_STRIDE + n] = v.y;
        As[(k4 * 4 + 2) * AS_STRIDE + n] = v.z;
        As[(k4 * 4 + 3) * AS_STRIDE + n] = v.w;
    }
    __syncthreads();

    int tx = tid & 31, ty = tid >> 5;

    unsigned long long acc[4][4];
    #pragma unroll
    for (int p = 0; p < 4; p++)
        #pragma unroll
        for (int j = 0; j < 4; j++) acc[p][j] = 0ull;

    uint32_t a_base = (uint32_t)__cvta_generic_to_shared(As) + ty * 32;
    const float* B0 = Ws + tx * 4;

    #pragma unroll 4
    for (int k = 0; k < 128; k++) {
        unsigned long long a01, a23, a45, a67;
        uint32_t aa = a_base + (uint32_t)k * (AS_STRIDE * 4);
        asm("ld.shared.v2.b64 {%0,%1}, [%2];" : "=l"(a01), "=l"(a23) : "r"(aa));
        asm("ld.shared.v2.b64 {%0,%1}, [%2];" : "=l"(a45), "=l"(a67) : "r"(aa + 16));
        float4 b = *(const float4*)(B0 + k * 128);
        unsigned long long bx = pack2(b.x), by = pack2(b.y),
                           bz = pack2(b.z), bw = pack2(b.w);
        FMA2(acc[0][0], a01, bx); FMA2(acc[0][1], a01, by);
        FMA2(acc[0][2], a01, bz); FMA2(acc[0][3], a01, bw);
        FMA2(acc[1][0], a23, bx); FMA2(acc[1][1], a23, by);
        FMA2(acc[1][2], a23, bz); FMA2(acc[1][3], a23, bw);
        FMA2(acc[2][0], a45, bx); FMA2(acc[2][1], a45, by);
        FMA2(acc[2][2], a45, bz); FMA2(acc[2][3], a45, bw);
        FMA2(acc[3][0], a67, bx); FMA2(acc[3][1], a67, by);
        FMA2(acc[3][2], a67, bz); FMA2(acc[3][3], a67, bw);
    }

    bool isZ = (tx < 16);
    float b0c = isZ ? __ldg(bias + tx * 4 + 0) : 0.f;
    float b1c = isZ ? __ldg(bias + tx * 4 + 1) : 0.f;
    float b2c = isZ ? __ldg(bias + tx * 4 + 2) : 0.f;
    float b3c = isZ ? __ldg(bias + tx * 4 + 3) : 0.f;
    int cbase = isZ ? tx * 4 : (tx - 16) * 4;

    #pragma unroll
    for (int p = 0; p < 4; p++) {
        float lo[4], hi[4];
        #pragma unroll
        for (int j = 0; j < 4; j++) {
            unsigned int l, h;
            asm("mov.b64 {%0,%1}, %2;" : "=r"(l), "=r"(h) : "l"(acc[p][j]));
            lo[j] = __uint_as_float(l);
            hi[j] = __uint_as_float(h);
        }
        int gn0 = n0 + ty * 8 + 2 * p;
        if (isZ) {
            if (gn0 < NN)
                *((float4*)(g_z + (size_t)gn0 * 64 + cbase)) =
                    make_float4(lo[0] + b0c, lo[1] + b1c, lo[2] + b2c, lo[3] + b3c);
            if (gn0 + 1 < NN)
                *((float4*)(g_z + (size_t)(gn0 + 1) * 64 + cbase)) =
                    make_float4(hi[0] + b0c, hi[1] + b1c, hi[2] + b2c, hi[3] + b3c);
        } else {
            if (gn0 < NN)
                *((uint2*)(g_y2h + (size_t)gn0 * 64 + cbase)) =
                    make_uint2(h2u(lo[0], lo[1]), h2u(lo[2], lo[3]));
            if (gn0 + 1 < NN)
                *((uint2*)(g_y2h + (size_t)(gn0 + 1) * 64 + cbase)) =
                    make_uint2(h2u(hi[0], hi[1]), h2u(hi[2], hi[3]));
        }
    }
}

// ---------------------------------------------------------------------------
// Aggregation 2 + epilogue: out = z + (sum_j y2h_j) * rinv2
// 8 lanes per node: lane covers 8 cols (16B fp16 per neighbor row).
// ---------------------------------------------------------------------------
__global__ __launch_bounds__(256) void k_agg2out(float* __restrict__ out) {
    int w = blockIdx.x * 32 + (threadIdx.x >> 3);
    if (w >= NN) return;
    int lane = threadIdx.x & 7;
    int beg = __ldg(g_rs + w);
    int cnt = __ldg(g_cnt + w);
    float rinv = __ldg(g_rinv2 + w);

    float acc[8] = {0.f, 0.f, 0.f, 0.f, 0.f, 0.f, 0.f, 0.f};
    int j = 0;
    for (; j + 8 <= cnt; j += 8) {
        int sidx[8];
        #pragma unroll
        for (int u = 0; u < 8; u++) sidx[u] = __ldg(g_csr + beg + j + u);
        uint4 r[8];
        #pragma unroll
        for (int u = 0; u < 8; u++)
            r[u] = *(const uint4*)(g_y2h + (size_t)sidx[u] * 64 + lane * 8);
        #pragma unroll
        for (int u = 0; u < 8; u++) {
            h2acc(r[u].x, acc[0], acc[1]);
            h2acc(r[u].y, acc[2], acc[3]);
            h2acc(r[u].z, acc[4], acc[5]);
            h2acc(r[u].w, acc[6], acc[7]);
        }
    }
    for (; j < cnt; j++) {
        int s = __ldg(g_csr + beg + j);
        uint4 r = *(const uint4*)(g_y2h + (size_t)s * 64 + lane * 8);
        h2acc(r.x, acc[0], acc[1]);
        h2acc(r.y, acc[2], acc[3]);
        h2acc(r.z, acc[4], acc[5]);
        h2acc(r.w, acc[6], acc[7]);
    }

    float4 z0 = *(const float4*)(g_z + (size_t)w * 64 + lane * 8);
    float4 z1 = *(const float4*)(g_z + (size_t)w * 64 + lane * 8 + 4);
    float4 o0, o1;
    o0.x = z0.x + acc[0] * rinv;
    o0.y = z0.y + acc[1] * rinv;
    o0.z = z0.z + acc[2] * rinv;
    o0.w = z0.w + acc[3] * rinv;
    o1.x = z1.x + acc[4] * rinv;
    o1.y = z1.y + acc[5] * rinv;
    o1.z = z1.z + acc[6] * rinv;
    o1.w = z1.w + acc[7] * rinv;
    *((float4*)(out + (size_t)w * 64 + lane * 8)) = o0;
    *((float4*)(out + (size_t)w * 64 + lane * 8 + 4)) = o1;
}

// ---------------------------------------------------------------------------
extern "C" void kernel_launch(void* const* d_in, const int* in_sizes, int n_in,
                              void* d_out, int out_size) {
    const float* x   = (const float*)d_in[0];
    const float* W1  = (const float*)d_in[1];
    const float* b1  = (const float*)d_in[2];
    const float* W2n = (const float*)d_in[3];
    const float* W2s = (const float*)d_in[4];
    const float* b2  = (const float*)d_in[5];
    const int*   ei  = (const int*)d_in[6];
    const int* src = ei;
    const int* dst = ei + EE;

    cudaFuncSetAttribute(k_m1, cudaFuncAttributeMaxDynamicSharedMemorySize, SMEM_GEMM);
    cudaFuncSetAttribute(k_m2, cudaFuncAttributeMaxDynamicSharedMemorySize, SMEM_GEMM);
    cudaFuncSetAttribute(k_gemm1, cudaFuncAttributeMaxDynamicSharedMemorySize, SMEM_GEMM);

    k_zero<<<(NN + 255) / 256, 256>>>();
    k_m1<<<HIST_BLOCKS + GA, 256, SMEM_GEMM>>>(x, W1, dst);       // hist || gemm0 A
    k_scan1<<<NB_SCAN, 1024>>>();
    k_scan3<<<(NN + 255) / 256, 256>>>();                         // scan2 inlined
    k_m2<<<FILL_BLOCKS + GB, 256, SMEM_GEMM>>>(x, W1, src, dst);  // fill || gemm0 B
    k_agg1b<<<(NN + 15) / 16, 256>>>(b1);
    k_gemm1<<<(NN + 63) / 64, 256, SMEM_GEMM>>>(W2s, W2n, b2);
    k_agg2out<<<(NN + 31) / 32, 256>>>((float*)d_out);
}

// round 12
// speedup vs baseline: 3.6227x; 1.6820x over previous
#include <cuda_runtime.h>
#include <cuda_fp16.h>
#include <cstdint>

#define NN 100000
#define EE 1600000
#define NB_SCAN 98          // ceil(NN/1024)
#define G0_BLOCKS 782       // ceil(NN/128)
#define HIST_BLOCKS 64
#define GA0 260             // gemm0 tiles merged with hist (M1)
#define GB0 (G0_BLOCKS - GA0)
#define FILL_BLOCKS 128

// ---------------- scratch (__device__ globals; no allocation allowed) ------
// NOTE: never pass these as host-side kernel arguments (host shadow symbol !=
// device address; caused the 128MiB-delta guard trips in R3-R6).
__device__ int    g_cnt[NN];
__device__ int    g_rs[NN];
__device__ int    g_cur[NN];
__device__ int    g_bsum[NB_SCAN];
__device__ float  g_rinv1[NN];
__device__ float  g_rinv2[NN];
__device__ int    g_csr[EE];
__device__ __half g_w1t[128 * 128];          // W1 transposed [n][k] fp16
__device__ __half g_w2t[128 * 128];          // [W2s|W2n] transposed [n][k] fp16
__device__ __half g_y1h[(size_t)NN * 128];   // x @ W1 (fp16)
__device__ __half g_h[(size_t)NN * 128];     // hidden activations (fp16)
__device__ __half g_y2h[(size_t)NN * 64];    // h @ W2n (fp16)
__device__ float  g_z[(size_t)NN * 64];      // h @ W2s + b2 (fp32)

// ---------------------------------------------------------------------------
// helpers
// ---------------------------------------------------------------------------
__device__ __forceinline__ unsigned int h2u(float a, float b) {
    __half2 h = __float22half2_rn(make_float2(a, b));
    return *(unsigned int*)&h;
}
__device__ __forceinline__ void h2acc(unsigned int u, float& a, float& b) {
    __half2 h = *(__half2*)&u;
    float2 f = __half22float2(h);
    a += f.x; b += f.y;
}

#define MMA16816(c, a0, a1, a2, a3, b0, b1)                                  \
    asm volatile(                                                            \
        "mma.sync.aligned.m16n8k16.row.col.f32.f16.f16.f32 "                 \
        "{%0,%1,%2,%3}, {%4,%5,%6,%7}, {%8,%9}, {%0,%1,%2,%3};"              \
        : "+f"((c)[0]), "+f"((c)[1]), "+f"((c)[2]), "+f"((c)[3])             \
        : "r"(a0), "r"(a1), "r"(a2), "r"(a3), "r"(b0), "r"(b1))

#define SMH_STRIDE 136   // halfs per smem row (128 + 8 pad)
#define SMEM_MMA (2 * 128 * SMH_STRIDE * 2)   // As + Bs, bytes = 69632

// ---------------------------------------------------------------------------
// k_prep: build fp16 transposed weights [n][k]
// ---------------------------------------------------------------------------
__global__ void k_prep(const float* __restrict__ W1,
                       const float* __restrict__ W2s,
                       const float* __restrict__ W2n) {
    int i = blockIdx.x * 256 + threadIdx.x;   // 16384
    if (i >= 16384) return;
    int n = i >> 7, k = i & 127;
    g_w1t[i] = __float2half(W1[k * 128 + n]);
    g_w2t[i] = __float2half(n < 64 ? W2s[k * 64 + n] : W2n[k * 64 + (n - 64)]);
}

// ---------------------------------------------------------------------------
// gemm0 tile (tensor core): y1h[128 x 128] = x_tile(fp16 cvt) @ W1
// 256 threads = 8 warps; warp = m32 x n64. Fragments via direct b32 LDS.
// ---------------------------------------------------------------------------
__device__ __forceinline__ void gemm0_tile(const float* __restrict__ x, int bid) {
    extern __shared__ __half smh[];
    __half* As = smh;                     // [row][k] 128 x 136
    __half* Bs = smh + 128 * SMH_STRIDE;  // [n][k]   128 x 136

    int tid = threadIdx.x;
    int r0 = bid * 128;

    // Bs <- g_w1t (dense [n][k]) as uint4 rows
    for (int i = tid; i < 2048; i += 256) {
        int n = i >> 4, c = i & 15;
        *((uint4*)(Bs + n * SMH_STRIDE) + c) = *((const uint4*)g_w1t + n * 16 + c);
    }
    // As <- x fp32 -> fp16
    for (int i = tid; i < 4096; i += 256) {
        int r = i >> 5, c4 = i & 31;
        int gn = r0 + r;
        float4 v = make_float4(0.f, 0.f, 0.f, 0.f);
        if (gn < NN) v = ((const float4*)(x + (size_t)gn * 128))[c4];
        *((uint2*)(As + r * SMH_STRIDE + c4 * 4)) =
            make_uint2(h2u(v.x, v.y), h2u(v.z, v.w));
    }
    __syncthreads();

    int w = tid >> 5, lane = tid & 31, g = lane >> 2, q = lane & 3;
    int mg = w >> 1, ng = w & 1;
    int mrow = mg * 32;

    float c[2][8][4];
    #pragma unroll
    for (int mt = 0; mt < 2; mt++)
        #pragma unroll
        for (int nt = 0; nt < 8; nt++)
            #pragma unroll
            for (int j = 0; j < 4; j++) c[mt][nt][j] = 0.f;

    #pragma unroll
    for (int ks = 0; ks < 8; ks++) {
        int kb = ks * 16;
        unsigned int a[2][4];
        #pragma unroll
        for (int mt = 0; mt < 2; mt++) {
            const __half* ap = As + (mrow + mt * 16 + g) * SMH_STRIDE + kb + q * 2;
            a[mt][0] = *(const unsigned int*)ap;
            a[mt][1] = *(const unsigned int*)(ap + 8 * SMH_STRIDE);
            a[mt][2] = *(const unsigned int*)(ap + 8);
            a[mt][3] = *(const unsigned int*)(ap + 8 * SMH_STRIDE + 8);
        }
        #pragma unroll
        for (int nt = 0; nt < 8; nt++) {
            const __half* bp = Bs + (ng * 64 + nt * 8 + g) * SMH_STRIDE + kb + q * 2;
            unsigned int b0 = *(const unsigned int*)bp;
            unsigned int b1 = *(const unsigned int*)(bp + 8);
            MMA16816(c[0][nt], a[0][0], a[0][1], a[0][2], a[0][3], b0, b1);
            MMA16816(c[1][nt], a[1][0], a[1][1], a[1][2], a[1][3], b0, b1);
        }
    }

    // epilogue -> y1h fp16
    #pragma unroll
    for (int mt = 0; mt < 2; mt++)
        #pragma unroll
        for (int nt = 0; nt < 8; nt++) {
            int row0 = r0 + mrow + mt * 16 + g;
            int col = ng * 64 + nt * 8 + q * 2;
            if (row0 < NN)
                *(unsigned int*)(g_y1h + (size_t)row0 * 128 + col) =
                    h2u(c[mt][nt][0], c[mt][nt][1]);
            if (row0 + 8 < NN)
                *(unsigned int*)(g_y1h + (size_t)(row0 + 8) * 128 + col) =
                    h2u(c[mt][nt][2], c[mt][nt][3]);
        }
}

// ---------------------------------------------------------------------------
// CSR build pieces
// ---------------------------------------------------------------------------
__global__ void k_zero() {
    int i = blockIdx.x * 256 + threadIdx.x;
    if (i < NN) g_cnt[i] = 0;
}

// M1: hist || gemm0 tiles [0, GA0)
__global__ void k_m1(const float* __restrict__ x, const int* __restrict__ dst) {
    if (blockIdx.x < HIST_BLOCKS) {
        for (int e = blockIdx.x * 256 + threadIdx.x; e < EE; e += HIST_BLOCKS * 256)
            atomicAdd(&g_cnt[__ldg(dst + e)], 1);
        return;
    }
    gemm0_tile(x, blockIdx.x - HIST_BLOCKS);
}

__global__ void k_scan1() {
    __shared__ int s[1024];
    int t = threadIdx.x;
    int i = blockIdx.x * 1024 + t;
    int v = (i < NN) ? g_cnt[i] : 0;
    s[t] = v;
    __syncthreads();
    #pragma unroll
    for (int off = 1; off < 1024; off <<= 1) {
        int u = (t >= off) ? s[t - off] : 0;
        __syncthreads();
        s[t] += u;
        __syncthreads();
    }
    if (i < NN) g_rs[i] = s[t] - v;
    if (t == 1023) g_bsum[blockIdx.x] = s[1023];
}

// scan3 with the 98-element block-sum scan inlined
__global__ void k_scan3() {
    __shared__ int ws[4];
    __shared__ int sbs[NB_SCAN];
    int t = threadIdx.x;
    int lane = t & 31, wid = t >> 5;
    int v = 0, s = 0;
    if (t < 128) {
        v = (t < NB_SCAN) ? g_bsum[t] : 0;
        s = v;
        #pragma unroll
        for (int off = 1; off < 32; off <<= 1) {
            int u = __shfl_up_sync(0xffffffffu, s, off);
            if (lane >= off) s += u;
        }
        if (lane == 31) ws[wid] = s;
    }
    __syncthreads();
    if (t < NB_SCAN) {
        int add = 0;
        #pragma unroll
        for (int w = 0; w < 4; w++) add += (w < wid) ? ws[w] : 0;
        sbs[t] = s + add - v;
    }
    __syncthreads();
    int i = blockIdx.x * 256 + t;
    if (i >= NN) return;
    int rs = g_rs[i] + sbs[i >> 10];
    g_rs[i] = rs;
    g_cur[i] = rs;
    float c = (float)g_cnt[i];
    g_rinv1[i] = 1.f / (c + 1.f);
    g_rinv2[i] = 1.f / fmaxf(c, 1.f);
}

// M2: fill || gemm0 tiles [GA0, 782)
__global__ void k_m2(const float* __restrict__ x,
                     const int* __restrict__ src,
                     const int* __restrict__ dst) {
    if (blockIdx.x < FILL_BLOCKS) {
        for (int e = blockIdx.x * 256 + threadIdx.x; e < EE; e += FILL_BLOCKS * 256) {
            int d = __ldg(dst + e);
            int pos = atomicAdd(&g_cur[d], 1);
            g_csr[pos] = __ldg(src + e);
        }
        return;
    }
    gemm0_tile(x, blockIdx.x - FILL_BLOCKS + GA0);
}

// ---------------------------------------------------------------------------
// Aggregation 1: h_i = relu((y1h_i + sum_j y1h_j)*rinv1 + b1), fp16 out
// Half-warp per node: 16 lanes x 8 cols (16B fp16/lane).
// ---------------------------------------------------------------------------
__global__ __launch_bounds__(256) void k_agg1b(const float* __restrict__ b1) {
    int w = blockIdx.x * 16 + (threadIdx.x >> 4);
    if (w >= NN) return;
    int lane = threadIdx.x & 15;
    int beg = __ldg(g_rs + w);
    int cnt = __ldg(g_cnt + w);
    float rinv = __ldg(g_rinv1 + w);

    float acc[8] = {0.f, 0.f, 0.f, 0.f, 0.f, 0.f, 0.f, 0.f};
    {   // self (fp16)
        uint4 r = *(const uint4*)(g_y1h + (size_t)w * 128 + lane * 8);
        h2acc(r.x, acc[0], acc[1]);
        h2acc(r.y, acc[2], acc[3]);
        h2acc(r.z, acc[4], acc[5]);
        h2acc(r.w, acc[6], acc[7]);
    }

    int j = 0;
    for (; j + 8 <= cnt; j += 8) {
        int sidx[8];
        #pragma unroll
        for (int u = 0; u < 8; u++) sidx[u] = __ldg(g_csr + beg + j + u);
        uint4 r[8];
        #pragma unroll
        for (int u = 0; u < 8; u++)
            r[u] = *(const uint4*)(g_y1h + (size_t)sidx[u] * 128 + lane * 8);
        #pragma unroll
        for (int u = 0; u < 8; u++) {
            h2acc(r[u].x, acc[0], acc[1]);
            h2acc(r[u].y, acc[2], acc[3]);
            h2acc(r[u].z, acc[4], acc[5]);
            h2acc(r[u].w, acc[6], acc[7]);
        }
    }
    for (; j < cnt; j++) {
        int s = __ldg(g_csr + beg + j);
        uint4 r = *(const uint4*)(g_y1h + (size_t)s * 128 + lane * 8);
        h2acc(r.x, acc[0], acc[1]);
        h2acc(r.y, acc[2], acc[3]);
        h2acc(r.z, acc[4], acc[5]);
        h2acc(r.w, acc[6], acc[7]);
    }

    float4 bb0 = *(const float4*)(b1 + lane * 8);
    float4 bb1 = *(const float4*)(b1 + lane * 8 + 4);
    float v0 = fmaxf(acc[0] * rinv + bb0.x, 0.f);
    float v1 = fmaxf(acc[1] * rinv + bb0.y, 0.f);
    float v2 = fmaxf(acc[2] * rinv + bb0.z, 0.f);
    float v3 = fmaxf(acc[3] * rinv + bb0.w, 0.f);
    float v4 = fmaxf(acc[4] * rinv + bb1.x, 0.f);
    float v5 = fmaxf(acc[5] * rinv + bb1.y, 0.f);
    float v6 = fmaxf(acc[6] * rinv + bb1.z, 0.f);
    float v7 = fmaxf(acc[7] * rinv + bb1.w, 0.f);
    uint4 o;
    o.x = h2u(v0, v1); o.y = h2u(v2, v3);
    o.z = h2u(v4, v5); o.w = h2u(v6, v7);
    *((uint4*)(g_h + (size_t)w * 128 + lane * 8)) = o;
}

// ---------------------------------------------------------------------------
// Layer-2 GEMM (tensor core): z(fp32,+b2) = h@W2s ; y2h(fp16) = h@W2n
// Same tiling as gemm0; A = g_h fp16 direct copy; B = g_w2t.
// ---------------------------------------------------------------------------
__global__ void k_gemm1(const float* __restrict__ bias) {
    extern __shared__ __half smh[];
    __half* As = smh;
    __half* Bs = smh + 128 * SMH_STRIDE;

    int tid = threadIdx.x;
    int r0 = blockIdx.x * 128;

    for (int i = tid; i < 2048; i += 256) {
        int n = i >> 4, c = i & 15;
        *((uint4*)(Bs + n * SMH_STRIDE) + c) = *((const uint4*)g_w2t + n * 16 + c);
    }
    for (int i = tid; i < 2048; i += 256) {
        int r = i >> 4, c = i & 15;
        int gn = r0 + r;
        uint4 v = make_uint4(0u, 0u, 0u, 0u);
        if (gn < NN) v = *((const uint4*)(g_h + (size_t)gn * 128) + c);
        *((uint4*)(As + r * SMH_STRIDE) + c) = v;
    }
    __syncthreads();

    int w = tid >> 5, lane = tid & 31, g = lane >> 2, q = lane & 3;
    int mg = w >> 1, ng = w & 1;
    int mrow = mg * 32;

    float c[2][8][4];
    #pragma unroll
    for (int mt = 0; mt < 2; mt++)
        #pragma unroll
        for (int nt = 0; nt < 8; nt++)
            #pragma unroll
            for (int j = 0; j < 4; j++) c[mt][nt][j] = 0.f;

    #pragma unroll
    for (int ks = 0; ks < 8; ks++) {
        int kb = ks * 16;
        unsigned int a[2][4];
        #pragma unroll
        for (int mt = 0; mt < 2; mt++) {
            const __half* ap = As + (mrow + mt * 16 + g) * SMH_STRIDE + kb + q * 2;
            a[mt][0] = *(const unsigned int*)ap;
            a[mt][1] = *(const unsigned int*)(ap + 8 * SMH_STRIDE);
            a[mt][2] = *(const unsigned int*)(ap + 8);
            a[mt][3] = *(const unsigned int*)(ap + 8 * SMH_STRIDE + 8);
        }
        #pragma unroll
        for (int nt = 0; nt < 8; nt++) {
            const __half* bp = Bs + (ng * 64 + nt * 8 + g) * SMH_STRIDE + kb + q * 2;
            unsigned int b0 = *(const unsigned int*)bp;
            unsigned int b1 = *(const unsigned int*)(bp + 8);
            MMA16816(c[0][nt], a[0][0], a[0][1], a[0][2], a[0][3], b0, b1);
            MMA16816(c[1][nt], a[1][0], a[1][1], a[1][2], a[1][3], b0, b1);
        }
    }

    // epilogue: ng==0 -> z fp32 (+bias); ng==1 -> y2h fp16
    #pragma unroll
    for (int mt = 0; mt < 2; mt++)
        #pragma unroll
        for (int nt = 0; nt < 8; nt++) {
            int row0 = r0 + mrow + mt * 16 + g;
            int col = ng * 64 + nt * 8 + q * 2;
            if (ng == 0) {
                float bz0 = __ldg(bias + col);
                float bz1 = __ldg(bias + col + 1);
                if (row0 < NN)
                    *(float2*)(g_z + (size_t)row0 * 64 + col) =
                        make_float2(c[mt][nt][0] + bz0, c[mt][nt][1] + bz1);
                if (row0 + 8 < NN)
                    *(float2*)(g_z + (size_t)(row0 + 8) * 64 + col) =
                        make_float2(c[mt][nt][2] + bz0, c[mt][nt][3] + bz1);
            } else {
                int c2 = col - 64;
                if (row0 < NN)
                    *(unsigned int*)(g_y2h + (size_t)row0 * 64 + c2) =
                        h2u(c[mt][nt][0], c[mt][nt][1]);
                if (row0 + 8 < NN)
                    *(unsigned int*)(g_y2h + (size_t)(row0 + 8) * 64 + c2) =
                        h2u(c[mt][nt][2], c[mt][nt][3]);
            }
        }
}

// ---------------------------------------------------------------------------
// Aggregation 2 + epilogue: out = z + (sum_j y2h_j) * rinv2
// 8 lanes per node (16B fp16 per neighbor row).
// ---------------------------------------------------------------------------
__global__ __launch_bounds__(256) void k_agg2out(float* __restrict__ out) {
    int w = blockIdx.x * 32 + (threadIdx.x >> 3);
    if (w >= NN) return;
    int lane = threadIdx.x & 7;
    int beg = __ldg(g_rs + w);
    int cnt = __ldg(g_cnt + w);
    float rinv = __ldg(g_rinv2 + w);

    float acc[8] = {0.f, 0.f, 0.f, 0.f, 0.f, 0.f, 0.f, 0.f};
    int j = 0;
    for (; j + 8 <= cnt; j += 8) {
        int sidx[8];
        #pragma unroll
        for (int u = 0; u < 8; u++) sidx[u] = __ldg(g_csr + beg + j + u);
        uint4 r[8];
        #pragma unroll
        for (int u = 0; u < 8; u++)
            r[u] = *(const uint4*)(g_y2h + (size_t)sidx[u] * 64 + lane * 8);
        #pragma unroll
        for (int u = 0; u < 8; u++) {
            h2acc(r[u].x, acc[0], acc[1]);
            h2acc(r[u].y, acc[2], acc[3]);
            h2acc(r[u].z, acc[4], acc[5]);
            h2acc(r[u].w, acc[6], acc[7]);
        }
    }
    for (; j < cnt; j++) {
        int s = __ldg(g_csr + beg + j);
        uint4 r = *(const uint4*)(g_y2h + (size_t)s * 64 + lane * 8);
        h2acc(r.x, acc[0], acc[1]);
        h2acc(r.y, acc[2], acc[3]);
        h2acc(r.z, acc[4], acc[5]);
        h2acc(r.w, acc[6], acc[7]);
    }

    float4 z0 = *(const float4*)(g_z + (size_t)w * 64 + lane * 8);
    float4 z1 = *(const float4*)(g_z + (size_t)w * 64 + lane * 8 + 4);
    float4 o0, o1;
    o0.x = z0.x + acc[0] * rinv;
    o0.y = z0.y + acc[1] * rinv;
    o0.z = z0.z + acc[2] * rinv;
    o0.w = z0.w + acc[3] * rinv;
    o1.x = z1.x + acc[4] * rinv;
    o1.y = z1.y + acc[5] * rinv;
    o1.z = z1.z + acc[6] * rinv;
    o1.w = z1.w + acc[7] * rinv;
    *((float4*)(out + (size_t)w * 64 + lane * 8)) = o0;
    *((float4*)(out + (size_t)w * 64 + lane * 8 + 4)) = o1;
}

// ---------------------------------------------------------------------------
extern "C" void kernel_launch(void* const* d_in, const int* in_sizes, int n_in,
                              void* d_out, int out_size) {
    const float* x   = (const float*)d_in[0];
    const float* W1  = (const float*)d_in[1];
    const float* b1  = (const float*)d_in[2];
    const float* W2n = (const float*)d_in[3];
    const float* W2s = (const float*)d_in[4];
    const float* b2  = (const float*)d_in[5];
    const int*   ei  = (const int*)d_in[6];
    const int* src = ei;
    const int* dst = ei + EE;

    cudaFuncSetAttribute(k_m1, cudaFuncAttributeMaxDynamicSharedMemorySize, SMEM_MMA);
    cudaFuncSetAttribute(k_m2, cudaFuncAttributeMaxDynamicSharedMemorySize, SMEM_MMA);
    cudaFuncSetAttribute(k_gemm1, cudaFuncAttributeMaxDynamicSharedMemorySize, SMEM_MMA);

    k_zero<<<(NN + 255) / 256, 256>>>();
    k_prep<<<64, 256>>>(W1, W2s, W2n);
    k_m1<<<HIST_BLOCKS + GA0, 256, SMEM_MMA>>>(x, dst);          // hist || gemm0 A
    k_scan1<<<NB_SCAN, 1024>>>();
    k_scan3<<<(NN + 255) / 256, 256>>>();
    k_m2<<<FILL_BLOCKS + GB0, 256, SMEM_MMA>>>(x, src, dst);     // fill || gemm0 B
    k_agg1b<<<(NN + 15) / 16, 256>>>(b1);
    k_gemm1<<<G0_BLOCKS, 256, SMEM_MMA>>>(b2);
    k_agg2out<<<(NN + 31) / 32, 256>>>((float*)d_out);
}